// round 1
// baseline (speedup 1.0000x reference)
#include <cuda_runtime.h>

#define D_MODEL   512
#define THREE_D   1536
#define M_TOK     32768      // 8 * 64 * 64 tokens
#define N_HEAD    16
#define HEAD_DIM  32
#define SCALE_Q   0.17677669529663689f   // 1/sqrt(32)
#define WS        64

// Scratch for qkv = x @ W^T + b  (201 MB, static device global -> allowed)
__device__ float g_qkv[(size_t)M_TOK * THREE_D];

// ---------------------------------------------------------------------------
// Kernel 1: qkv[t, j] = sum_c x[t,c] * w[j,c] + b[j]   (q rows j<512 scaled)
// BM=BN=128, BK=16, 256 threads, 8x8 register tile, double-buffered SMEM.
// ---------------------------------------------------------------------------
__global__ __launch_bounds__(256, 2)
void qkv_gemm(const float* __restrict__ x,
              const float* __restrict__ w,
              const float* __restrict__ b) {
    __shared__ float As[2][16][128];
    __shared__ float Bs[2][16][128];

    const int tid  = threadIdx.x;
    const int tx   = tid & 15;        // n-tile (8 cols)
    const int ty   = tid >> 4;        // m-tile (8 rows)
    const int lrow = tid >> 1;        // 0..127 : row loaded by this thread
    const int lk   = (tid & 1) * 8;   // 0 or 8 : k-offset loaded

    const float* xg = x + (size_t)(blockIdx.y * 128 + lrow) * D_MODEL + lk;
    const float* wg = w + (size_t)(blockIdx.x * 128 + lrow) * D_MODEL + lk;

    float acc[8][8];
#pragma unroll
    for (int i = 0; i < 8; ++i)
#pragma unroll
        for (int j = 0; j < 8; ++j) acc[i][j] = 0.f;

    // prefetch tile 0
    float4 pa0 = *(const float4*)(xg);
    float4 pa1 = *(const float4*)(xg + 4);
    float4 pb0 = *(const float4*)(wg);
    float4 pb1 = *(const float4*)(wg + 4);
    xg += 16; wg += 16;

    {   // store tile 0 into buffer 0 (k-transposed)
        As[0][lk+0][lrow]=pa0.x; As[0][lk+1][lrow]=pa0.y; As[0][lk+2][lrow]=pa0.z; As[0][lk+3][lrow]=pa0.w;
        As[0][lk+4][lrow]=pa1.x; As[0][lk+5][lrow]=pa1.y; As[0][lk+6][lrow]=pa1.z; As[0][lk+7][lrow]=pa1.w;
        Bs[0][lk+0][lrow]=pb0.x; Bs[0][lk+1][lrow]=pb0.y; Bs[0][lk+2][lrow]=pb0.z; Bs[0][lk+3][lrow]=pb0.w;
        Bs[0][lk+4][lrow]=pb1.x; Bs[0][lk+5][lrow]=pb1.y; Bs[0][lk+6][lrow]=pb1.z; Bs[0][lk+7][lrow]=pb1.w;
    }

    const int NT = D_MODEL / 16;   // 32 k-tiles
    for (int kt = 0; kt < NT; ++kt) {
        __syncthreads();
        const int buf = kt & 1;

        if (kt + 1 < NT) {
            pa0 = *(const float4*)(xg);
            pa1 = *(const float4*)(xg + 4);
            pb0 = *(const float4*)(wg);
            pb1 = *(const float4*)(wg + 4);
            xg += 16; wg += 16;
        }

#pragma unroll
        for (int k = 0; k < 16; ++k) {
            float4 a0 = *(const float4*)&As[buf][k][ty * 8];
            float4 a1 = *(const float4*)&As[buf][k][ty * 8 + 4];
            float4 b0v = *(const float4*)&Bs[buf][k][tx * 8];
            float4 b1v = *(const float4*)&Bs[buf][k][tx * 8 + 4];
            float av[8] = {a0.x,a0.y,a0.z,a0.w,a1.x,a1.y,a1.z,a1.w};
            float bv[8] = {b0v.x,b0v.y,b0v.z,b0v.w,b1v.x,b1v.y,b1v.z,b1v.w};
#pragma unroll
            for (int i = 0; i < 8; ++i)
#pragma unroll
                for (int j = 0; j < 8; ++j)
                    acc[i][j] += av[i] * bv[j];
        }

        if (kt + 1 < NT) {
            const int nb = buf ^ 1;
            As[nb][lk+0][lrow]=pa0.x; As[nb][lk+1][lrow]=pa0.y; As[nb][lk+2][lrow]=pa0.z; As[nb][lk+3][lrow]=pa0.w;
            As[nb][lk+4][lrow]=pa1.x; As[nb][lk+5][lrow]=pa1.y; As[nb][lk+6][lrow]=pa1.z; As[nb][lk+7][lrow]=pa1.w;
            Bs[nb][lk+0][lrow]=pb0.x; Bs[nb][lk+1][lrow]=pb0.y; Bs[nb][lk+2][lrow]=pb0.z; Bs[nb][lk+3][lrow]=pb0.w;
            Bs[nb][lk+4][lrow]=pb1.x; Bs[nb][lk+5][lrow]=pb1.y; Bs[nb][lk+6][lrow]=pb1.z; Bs[nb][lk+7][lrow]=pb1.w;
        }
    }

    // epilogue: bias + scale (q block only) + store
    const int mg = blockIdx.y * 128 + ty * 8;
    const int ng = blockIdx.x * 128 + tx * 8;
    const float scale = (blockIdx.x < 4) ? SCALE_Q : 1.0f;

    float4 bb0 = *(const float4*)&b[ng];
    float4 bb1 = *(const float4*)&b[ng + 4];
    float bias[8] = {bb0.x,bb0.y,bb0.z,bb0.w,bb1.x,bb1.y,bb1.z,bb1.w};

#pragma unroll
    for (int i = 0; i < 8; ++i) {
        float* o = &g_qkv[(size_t)(mg + i) * THREE_D + ng];
        float4 v0, v1;
        v0.x=(acc[i][0]+bias[0])*scale; v0.y=(acc[i][1]+bias[1])*scale;
        v0.z=(acc[i][2]+bias[2])*scale; v0.w=(acc[i][3]+bias[3])*scale;
        v1.x=(acc[i][4]+bias[4])*scale; v1.y=(acc[i][5]+bias[5])*scale;
        v1.z=(acc[i][6]+bias[6])*scale; v1.w=(acc[i][7]+bias[7])*scale;
        *(float4*)(o)     = v0;
        *(float4*)(o + 4) = v1;
    }
}

// ---------------------------------------------------------------------------
// Kernel 2: per (window, head) attention.
// blockIdx.x = head (16), blockIdx.y = window (512). 256 threads.
// ---------------------------------------------------------------------------
__device__ __forceinline__ int region_id(int g) {
    // H=W=64, window 8, shift 4: rows [0,56)->0, [56,60)->1, [60,64)->2
    return g < 56 ? 0 : (g < 60 ? 1 : 2);
}

__global__ __launch_bounds__(256)
void win_attn(const float* __restrict__ bias_table, float* __restrict__ out) {
    const int head = blockIdx.x;
    const int wdx  = blockIdx.y;
    const int n  = wdx >> 6;
    const int r  = wdx & 63;
    const int wh = r >> 3;
    const int ww = r & 7;

    __shared__ float Qs[64][32];
    __shared__ float Kt[32][64];     // K transposed: Kt[d][j]
    __shared__ float Vs[64][32];
    __shared__ float Ps[64][68];     // scores -> probabilities (68: pad, rows 16B-aligned)
    __shared__ float bias_s[225];

    const int tid = threadIdx.x;

    for (int i2 = tid; i2 < 225; i2 += 256)
        bias_s[i2] = bias_table[i2 * N_HEAD + head];

    // load Q, K (transposed), V for this window+head
#pragma unroll
    for (int pass = 0; pass < 2; ++pass) {
        int idx = tid + pass * 256;                 // 0..511
        int row = idx >> 3;                         // token pos in window
        int c4  = (idx & 7) * 4;                    // d offset
        int tok = ((n * 64 + wh * 8 + (row >> 3)) * 64 + ww * 8 + (row & 7));
        const float* base = g_qkv + (size_t)tok * THREE_D + head * HEAD_DIM + c4;
        float4 qv = *(const float4*)(base);
        float4 kv = *(const float4*)(base + 512);
        float4 vv = *(const float4*)(base + 1024);
        *(float4*)&Qs[row][c4] = qv;
        Kt[c4 + 0][row] = kv.x; Kt[c4 + 1][row] = kv.y;
        Kt[c4 + 2][row] = kv.z; Kt[c4 + 3][row] = kv.w;
        *(float4*)&Vs[row][c4] = vv;
    }
    __syncthreads();

    // ---- phase 1: S = Q K^T + bias + mask -> Ps
    const int ti = tid >> 4, tj = tid & 15;
    const int i0 = ti * 4, j0 = tj * 4;
    {
        float acc[4][4];
#pragma unroll
        for (int a = 0; a < 4; ++a)
#pragma unroll
            for (int c = 0; c < 4; ++c) acc[a][c] = 0.f;

#pragma unroll
        for (int kc = 0; kc < 4; ++kc) {
            float qreg[4][8];
#pragma unroll
            for (int a = 0; a < 4; ++a) {
                *(float4*)&qreg[a][0] = *(const float4*)&Qs[i0 + a][kc * 8];
                *(float4*)&qreg[a][4] = *(const float4*)&Qs[i0 + a][kc * 8 + 4];
            }
#pragma unroll
            for (int kk = 0; kk < 8; ++kk) {
                float4 kvv = *(const float4*)&Kt[kc * 8 + kk][j0];
#pragma unroll
                for (int a = 0; a < 4; ++a) {
                    float qe = qreg[a][kk];
                    acc[a][0] += qe * kvv.x;
                    acc[a][1] += qe * kvv.y;
                    acc[a][2] += qe * kvv.z;
                    acc[a][3] += qe * kvv.w;
                }
            }
        }

#pragma unroll
        for (int a = 0; a < 4; ++a) {
            const int i  = i0 + a;
            const int mi = region_id(wh * 8 + (i >> 3)) * 3 + region_id(ww * 8 + (i & 7));
#pragma unroll
            for (int c = 0; c < 4; ++c) {
                const int j  = j0 + c;
                const int d0 = (i >> 3) - (j >> 3) + 7;
                const int d1 = (i & 7)  - (j & 7)  + 7;
                float bm = bias_s[d0 * 15 + d1];
                const int mj = region_id(wh * 8 + (j >> 3)) * 3 + region_id(ww * 8 + (j & 7));
                if (mi != mj) bm -= 100.f;
                Ps[i][j] = acc[a][c] + bm;
            }
        }
    }
    __syncthreads();

    // ---- phase 2: row softmax (warp handles 8 rows, 2 elems/lane)
    {
        const int lane = tid & 31, warp = tid >> 5;
#pragma unroll
        for (int rr = 0; rr < 8; ++rr) {
            const int row = warp * 8 + rr;
            float x0 = Ps[row][lane];
            float x1 = Ps[row][lane + 32];
            float m = fmaxf(x0, x1);
#pragma unroll
            for (int off = 16; off > 0; off >>= 1)
                m = fmaxf(m, __shfl_xor_sync(0xffffffffu, m, off));
            float e0 = __expf(x0 - m);
            float e1 = __expf(x1 - m);
            float s = e0 + e1;
#pragma unroll
            for (int off = 16; off > 0; off >>= 1)
                s += __shfl_xor_sync(0xffffffffu, s, off);
            const float inv = 1.0f / s;
            Ps[row][lane]      = e0 * inv;
            Ps[row][lane + 32] = e1 * inv;
        }
    }
    __syncthreads();

    // ---- phase 3: O = P V ; thread computes 4 rows x 2 dims
    {
        const int dd = tj * 2;
        float o[4][2];
#pragma unroll
        for (int a = 0; a < 4; ++a) { o[a][0] = 0.f; o[a][1] = 0.f; }

#pragma unroll
        for (int jc = 0; jc < 16; ++jc) {
            float pr[4][4];
#pragma unroll
            for (int a = 0; a < 4; ++a)
                *(float4*)&pr[a][0] = *(const float4*)&Ps[i0 + a][jc * 4];
            float2 vv[4];
#pragma unroll
            for (int u = 0; u < 4; ++u)
                vv[u] = *(const float2*)&Vs[jc * 4 + u][dd];
#pragma unroll
            for (int a = 0; a < 4; ++a)
#pragma unroll
                for (int u = 0; u < 4; ++u) {
                    o[a][0] += pr[a][u] * vv[u].x;
                    o[a][1] += pr[a][u] * vv[u].y;
                }
        }

#pragma unroll
        for (int a = 0; a < 4; ++a) {
            const int i   = i0 + a;
            const int tok = ((n * 64 + wh * 8 + (i >> 3)) * 64 + ww * 8 + (i & 7));
            float2* dst = (float2*)(out + (size_t)tok * D_MODEL + head * HEAD_DIM + dd);
            *dst = make_float2(o[a][0], o[a][1]);
        }
    }
}

// ---------------------------------------------------------------------------
extern "C" void kernel_launch(void* const* d_in, const int* in_sizes, int n_in,
                              void* d_out, int out_size) {
    const float* x  = (const float*)d_in[0];   // (8,64,64,512) f32
    const float* w  = (const float*)d_in[1];   // (1536,512)   f32
    const float* b  = (const float*)d_in[2];   // (1536,)      f32
    const float* bt = (const float*)d_in[3];   // (225,16)     f32
    float* out = (float*)d_out;                // (8,64,64,512) f32

    dim3 g1(THREE_D / 128, M_TOK / 128);       // (12, 256)
    qkv_gemm<<<g1, 256>>>(x, w, b);

    dim3 g2(N_HEAD, 512);                      // head, window
    win_attn<<<g2, 256>>>(bt, out);
}

// round 3
// speedup vs baseline: 1.5690x; 1.5690x over previous
#include <cuda_runtime.h>
#include <cstdint>

#define D_MODEL   512
#define THREE_D   1536
#define M_TOK     32768      // 8 * 64 * 64 tokens
#define N_HEAD    16
#define HEAD_DIM  32
#define SCALE_Q   0.17677669529663689f   // 1/sqrt(32)

// Scratch for qkv = x @ W^T + b  (201 MB, static device global -> allowed)
__device__ float g_qkv[(size_t)M_TOK * THREE_D];

__device__ __forceinline__ uint32_t f2tf32(float f) {
    uint32_t u;
    asm("cvt.rna.tf32.f32 %0, %1;" : "=r"(u) : "f"(f));
    return u;
}

__device__ __forceinline__ void mma_tf32(float* c, uint4 a, uint32_t b0, uint32_t b1) {
    asm volatile(
        "mma.sync.aligned.m16n8k8.row.col.f32.tf32.tf32.f32 "
        "{%0,%1,%2,%3}, {%4,%5,%6,%7}, {%8,%9}, {%0,%1,%2,%3};\n"
        : "+f"(c[0]), "+f"(c[1]), "+f"(c[2]), "+f"(c[3])
        : "r"(a.x), "r"(a.y), "r"(a.z), "r"(a.w), "r"(b0), "r"(b1));
}

// ---------------------------------------------------------------------------
// Kernel 1: qkv[t, j] = sum_c x[t,c] * w[j,c] + b[j]   (tf32 tensor cores)
// BM=BN=128, BK=32. 256 threads = 8 warps as 2(m) x 4(n); warp tile 64x32.
// SMEM holds fragment-permuted quads -> conflict-free LDS.128 fragment loads.
// ---------------------------------------------------------------------------
__global__ __launch_bounds__(256, 2)
void qkv_gemm_tc(const float* __restrict__ x,
                 const float* __restrict__ w,
                 const float* __restrict__ bias_vec) {
    // A: [mfrag 8][ks 4][lane 32][4]  = 4096 u32 (16 KB)
    // B: [nfrag 16][kpair 2][lane 32][4] = 4096 u32 (16 KB)
    __shared__ uint32_t sA[4096];
    __shared__ uint32_t sB[4096];

    const int tid = threadIdx.x;
    const int r   = tid >> 1;          // 0..127 row within tile (for loading)
    const int ch16 = (tid & 1) * 16;   // k-offset 0 or 16
    const int bm  = blockIdx.y * 128;
    const int bn  = blockIdx.x * 128;

    const int warp = tid >> 5, lane = tid & 31;
    const int wm = warp >> 2, wn = warp & 3;   // 2 x 4 warp grid

    float acc[4][4][4];
#pragma unroll
    for (int m = 0; m < 4; ++m)
#pragma unroll
        for (int n = 0; n < 4; ++n)
#pragma unroll
            for (int q = 0; q < 4; ++q) acc[m][n][q] = 0.f;

    const float* xg = x + (size_t)(bm + r) * D_MODEL + ch16;
    const float* wg = w + (size_t)(bn + r) * D_MODEL + ch16;

    const int rot  = ((r >> 1) + (tid & 1) * 2) & 3;  // store-conflict rotation
    const int g    = r & 7;
    const int mf   = r >> 4;           // A mfrag of loaded row
    const int half = (r >> 3) & 1;     // A row-half (+8)
    const int nf   = r >> 3;           // B nfrag of loaded row

    for (int kt = 0; kt < D_MODEL / 32; ++kt) {
        // ---- load 32-wide k-chunk, convert to tf32, scatter to frag layout
#pragma unroll
        for (int jj = 0; jj < 4; ++jj) {
            float4 va = *(const float4*)(xg + jj * 4);
            float4 vb = *(const float4*)(wg + jj * 4);
            uint32_t ua[4] = {f2tf32(va.x), f2tf32(va.y), f2tf32(va.z), f2tf32(va.w)};
            uint32_t ub[4] = {f2tf32(vb.x), f2tf32(vb.y), f2tf32(vb.z), f2tf32(vb.w)};
#pragma unroll
            for (int tt = 0; tt < 4; ++tt) {
                const int t  = (tt + rot) & 3;
                const int c  = ch16 + jj * 4 + t;      // k within chunk 0..31
                const int ks = c >> 3;
                const int tg = c & 3;
                // A quad component: idx = half + 2*((c>>2)&1)
                sA[((mf * 4 + ks) * 32 + g * 4 + tg) * 4 + (half + 2 * ((c >> 2) & 1))] = ua[t];
                // B quad component: idx = (c>>2)&3, kpair = c>>4
                sB[((nf * 2 + (c >> 4)) * 32 + g * 4 + tg) * 4 + ((c >> 2) & 3)] = ub[t];
            }
        }
        xg += 32; wg += 32;
        __syncthreads();

        // ---- compute: 4 k-steps of m16n8k8
        uint4 bq[4];
#pragma unroll
        for (int ks = 0; ks < 4; ++ks) {
            if ((ks & 1) == 0) {
#pragma unroll
                for (int n = 0; n < 4; ++n)
                    bq[n] = *(const uint4*)&sB[(((wn * 4 + n) * 2 + (ks >> 1)) * 32 + lane) * 4];
            }
            uint4 af[4];
#pragma unroll
            for (int m = 0; m < 4; ++m)
                af[m] = *(const uint4*)&sA[(((wm * 4 + m) * 4 + ks) * 32 + lane) * 4];
#pragma unroll
            for (int m = 0; m < 4; ++m)
#pragma unroll
                for (int n = 0; n < 4; ++n) {
                    const uint32_t b0 = (ks & 1) ? bq[n].z : bq[n].x;
                    const uint32_t b1 = (ks & 1) ? bq[n].w : bq[n].y;
                    mma_tf32(acc[m][n], af[m], b0, b1);
                }
        }
        __syncthreads();
    }

    // ---- epilogue: bias + q-scale + store
    const float scale = (blockIdx.x < 4) ? SCALE_Q : 1.0f;
    const int gq = lane >> 2, tq = lane & 3;
#pragma unroll
    for (int n = 0; n < 4; ++n) {
        const int col = bn + wn * 32 + n * 8 + tq * 2;
        const float bx = bias_vec[col];
        const float by = bias_vec[col + 1];
#pragma unroll
        for (int m = 0; m < 4; ++m) {
            const int row0 = bm + wm * 64 + m * 16 + gq;
            float* o0 = &g_qkv[(size_t)row0 * THREE_D + col];
            *(float2*)o0 = make_float2((acc[m][n][0] + bx) * scale,
                                       (acc[m][n][1] + by) * scale);
            float* o1 = o0 + (size_t)8 * THREE_D;
            *(float2*)o1 = make_float2((acc[m][n][2] + bx) * scale,
                                       (acc[m][n][3] + by) * scale);
        }
    }
}

// ---------------------------------------------------------------------------
// Kernel 2: per (window, head) attention.  (unchanged from round 1)
// ---------------------------------------------------------------------------
__device__ __forceinline__ int region_id(int g) {
    return g < 56 ? 0 : (g < 60 ? 1 : 2);
}

__global__ __launch_bounds__(256)
void win_attn(const float* __restrict__ bias_table, float* __restrict__ out) {
    const int head = blockIdx.x;
    const int wdx  = blockIdx.y;
    const int n  = wdx >> 6;
    const int r  = wdx & 63;
    const int wh = r >> 3;
    const int ww = r & 7;

    __shared__ float Qs[64][32];
    __shared__ float Kt[32][64];
    __shared__ float Vs[64][32];
    __shared__ float Ps[64][68];
    __shared__ float bias_s[225];

    const int tid = threadIdx.x;

    for (int i2 = tid; i2 < 225; i2 += 256)
        bias_s[i2] = bias_table[i2 * N_HEAD + head];

#pragma unroll
    for (int pass = 0; pass < 2; ++pass) {
        int idx = tid + pass * 256;
        int row = idx >> 3;
        int c4  = (idx & 7) * 4;
        int tok = ((n * 64 + wh * 8 + (row >> 3)) * 64 + ww * 8 + (row & 7));
        const float* base = g_qkv + (size_t)tok * THREE_D + head * HEAD_DIM + c4;
        float4 qv = *(const float4*)(base);
        float4 kv = *(const float4*)(base + 512);
        float4 vv = *(const float4*)(base + 1024);
        *(float4*)&Qs[row][c4] = qv;
        Kt[c4 + 0][row] = kv.x; Kt[c4 + 1][row] = kv.y;
        Kt[c4 + 2][row] = kv.z; Kt[c4 + 3][row] = kv.w;
        *(float4*)&Vs[row][c4] = vv;
    }
    __syncthreads();

    const int ti = tid >> 4, tj = tid & 15;
    const int i0 = ti * 4, j0 = tj * 4;
    {
        float acc[4][4];
#pragma unroll
        for (int a = 0; a < 4; ++a)
#pragma unroll
            for (int c = 0; c < 4; ++c) acc[a][c] = 0.f;

#pragma unroll
        for (int kc = 0; kc < 4; ++kc) {
            float qreg[4][8];
#pragma unroll
            for (int a = 0; a < 4; ++a) {
                *(float4*)&qreg[a][0] = *(const float4*)&Qs[i0 + a][kc * 8];
                *(float4*)&qreg[a][4] = *(const float4*)&Qs[i0 + a][kc * 8 + 4];
            }
#pragma unroll
            for (int kk = 0; kk < 8; ++kk) {
                float4 kvv = *(const float4*)&Kt[kc * 8 + kk][j0];
#pragma unroll
                for (int a = 0; a < 4; ++a) {
                    float qe = qreg[a][kk];
                    acc[a][0] += qe * kvv.x;
                    acc[a][1] += qe * kvv.y;
                    acc[a][2] += qe * kvv.z;
                    acc[a][3] += qe * kvv.w;
                }
            }
        }

#pragma unroll
        for (int a = 0; a < 4; ++a) {
            const int i  = i0 + a;
            const int mi = region_id(wh * 8 + (i >> 3)) * 3 + region_id(ww * 8 + (i & 7));
#pragma unroll
            for (int c = 0; c < 4; ++c) {
                const int j  = j0 + c;
                const int d0 = (i >> 3) - (j >> 3) + 7;
                const int d1 = (i & 7)  - (j & 7)  + 7;
                float bm = bias_s[d0 * 15 + d1];
                const int mj = region_id(wh * 8 + (j >> 3)) * 3 + region_id(ww * 8 + (j & 7));
                if (mi != mj) bm -= 100.f;
                Ps[i][j] = acc[a][c] + bm;
            }
        }
    }
    __syncthreads();

    {
        const int lane = tid & 31, warp = tid >> 5;
#pragma unroll
        for (int rr = 0; rr < 8; ++rr) {
            const int row = warp * 8 + rr;
            float x0 = Ps[row][lane];
            float x1 = Ps[row][lane + 32];
            float m = fmaxf(x0, x1);
#pragma unroll
            for (int off = 16; off > 0; off >>= 1)
                m = fmaxf(m, __shfl_xor_sync(0xffffffffu, m, off));
            float e0 = __expf(x0 - m);
            float e1 = __expf(x1 - m);
            float s = e0 + e1;
#pragma unroll
            for (int off = 16; off > 0; off >>= 1)
                s += __shfl_xor_sync(0xffffffffu, s, off);
            const float inv = 1.0f / s;
            Ps[row][lane]      = e0 * inv;
            Ps[row][lane + 32] = e1 * inv;
        }
    }
    __syncthreads();

    {
        const int dd = tj * 2;
        float o[4][2];
#pragma unroll
        for (int a = 0; a < 4; ++a) { o[a][0] = 0.f; o[a][1] = 0.f; }

#pragma unroll
        for (int jc = 0; jc < 16; ++jc) {
            float pr[4][4];
#pragma unroll
            for (int a = 0; a < 4; ++a)
                *(float4*)&pr[a][0] = *(const float4*)&Ps[i0 + a][jc * 4];
            float2 vv[4];
#pragma unroll
            for (int u = 0; u < 4; ++u)
                vv[u] = *(const float2*)&Vs[jc * 4 + u][dd];
#pragma unroll
            for (int a = 0; a < 4; ++a)
#pragma unroll
                for (int u = 0; u < 4; ++u) {
                    o[a][0] += pr[a][u] * vv[u].x;
                    o[a][1] += pr[a][u] * vv[u].y;
                }
        }

#pragma unroll
        for (int a = 0; a < 4; ++a) {
            const int i   = i0 + a;
            const int tok = ((n * 64 + wh * 8 + (i >> 3)) * 64 + ww * 8 + (i & 7));
            float2* dst = (float2*)(out + (size_t)tok * D_MODEL + head * HEAD_DIM + dd);
            *dst = make_float2(o[a][0], o[a][1]);
        }
    }
}

// ---------------------------------------------------------------------------
extern "C" void kernel_launch(void* const* d_in, const int* in_sizes, int n_in,
                              void* d_out, int out_size) {
    const float* x  = (const float*)d_in[0];   // (8,64,64,512) f32
    const float* w  = (const float*)d_in[1];   // (1536,512)   f32
    const float* b  = (const float*)d_in[2];   // (1536,)      f32
    const float* bt = (const float*)d_in[3];   // (225,16)     f32
    float* out = (float*)d_out;                // (8,64,64,512) f32

    dim3 g1(THREE_D / 128, M_TOK / 128);       // (12, 256)
    qkv_gemm_tc<<<g1, 256>>>(x, w, b);

    dim3 g2(N_HEAD, 512);                      // head, window
    win_attn<<<g2, 256>>>(bt, out);
}

// round 4
// speedup vs baseline: 2.8518x; 1.8176x over previous
#include <cuda_runtime.h>
#include <cstdint>

#define D_MODEL   512
#define THREE_D   1536
#define M_TOK     32768      // 8 * 64 * 64 tokens
#define N_HEAD    16
#define HEAD_DIM  32
#define SCALE_Q   0.17677669529663689f   // 1/sqrt(32)
#define STAGES    3
#define NKT       16         // 512 / 32

// Device-global scratch (allocation-guard-safe)
__device__ float g_qkv[(size_t)M_TOK * THREE_D];          // 201 MB
__device__ float g_xr[(size_t)M_TOK * D_MODEL];           // 64 MB  tf32-rounded x
__device__ float g_wr[(size_t)THREE_D * D_MODEL];         // 3 MB   tf32-rounded w

__device__ __forceinline__ uint32_t f2tf32(float f) {
    uint32_t u;
    asm("cvt.rna.tf32.f32 %0, %1;" : "=r"(u) : "f"(f));
    return u;
}

__device__ __forceinline__ void ldsm4(uint32_t& r0, uint32_t& r1, uint32_t& r2,
                                      uint32_t& r3, uint32_t addr) {
    asm volatile("ldmatrix.sync.aligned.m8n8.x4.shared.b16 {%0,%1,%2,%3}, [%4];"
                 : "=r"(r0), "=r"(r1), "=r"(r2), "=r"(r3) : "r"(addr));
}

__device__ __forceinline__ void mma_tf32(float* c, const uint32_t* a,
                                         uint32_t b0, uint32_t b1) {
    asm volatile(
        "mma.sync.aligned.m16n8k8.row.col.f32.tf32.tf32.f32 "
        "{%0,%1,%2,%3}, {%4,%5,%6,%7}, {%8,%9}, {%0,%1,%2,%3};\n"
        : "+f"(c[0]), "+f"(c[1]), "+f"(c[2]), "+f"(c[3])
        : "r"(a[0]), "r"(a[1]), "r"(a[2]), "r"(a[3]), "r"(b0), "r"(b1));
}

// ---------------------------------------------------------------------------
// Pre-pass: round f32 -> tf32 (stored as f32 bits with low mantissa zeroed)
// ---------------------------------------------------------------------------
__global__ void round_tf32(const float* __restrict__ in, float* __restrict__ out, int n4) {
    int i = blockIdx.x * 256 + threadIdx.x;
    if (i >= n4) return;
    float4 v = ((const float4*)in)[i];
    uint4 o;
    o.x = f2tf32(v.x); o.y = f2tf32(v.y); o.z = f2tf32(v.z); o.w = f2tf32(v.w);
    ((uint4*)out)[i] = o;
}

// ---------------------------------------------------------------------------
// Kernel 1: qkv = xr @ wr^T + b  (tf32 mma, cp.async 3-stage pipeline)
// BM=BN=128, BK=32. 8 warps as 2(m) x 4(n); warp tile 64x32.
// SMEM tiles: raw row-major f32 [row][32k], 16B chunks XOR-swizzled
// (chunk' = c ^ (row&7)) -> conflict-free cp.async stores + ldmatrix reads.
// ---------------------------------------------------------------------------
__global__ __launch_bounds__(256, 2)
void qkv_gemm_tc(const float* __restrict__ xr,
                 const float* __restrict__ wr,
                 const float* __restrict__ bias_vec) {
    extern __shared__ uint32_t smem[];   // STAGES * (A 16KB + B 16KB)
    const uint32_t smem_base = (uint32_t)__cvta_generic_to_shared(smem);

    const int tid  = threadIdx.x;
    const int lane = tid & 31, warp = tid >> 5;
    const int wm = warp >> 2, wn = warp & 3;        // 2 x 4 warp grid
    const int bm = blockIdx.y * 128, bn = blockIdx.x * 128;

    // ---- loader setup: 4 A-chunks + 4 B-chunks (16B each) per thread
    const float* aptr[4];
    const float* bptr[4];
    uint32_t swz[4];
#pragma unroll
    for (int i = 0; i < 4; ++i) {
        const int id  = i * 256 + tid;              // 0..1023
        const int row = id >> 3, c = id & 7;
        swz[i]  = (uint32_t)(row * 8 + (c ^ (row & 7))) * 16;
        aptr[i] = xr + (size_t)(bm + row) * D_MODEL + c * 4;
        bptr[i] = wr + (size_t)(bn + row) * D_MODEL + c * 4;
    }

    auto issue = [&](int kt, int s) {
        const uint32_t ab = smem_base + s * 32768;
        const uint32_t bb = ab + 16384;
#pragma unroll
        for (int i = 0; i < 4; ++i) {
            asm volatile("cp.async.cg.shared.global [%0], [%1], 16;"
                         :: "r"(ab + swz[i]), "l"(aptr[i] + kt * 32));
            asm volatile("cp.async.cg.shared.global [%0], [%1], 16;"
                         :: "r"(bb + swz[i]), "l"(bptr[i] + kt * 32));
        }
        asm volatile("cp.async.commit_group;");
    };

    float acc[4][4][4];
#pragma unroll
    for (int m = 0; m < 4; ++m)
#pragma unroll
        for (int n = 0; n < 4; ++n)
#pragma unroll
            for (int q = 0; q < 4; ++q) acc[m][n][q] = 0.f;

    // per-lane fragment addressing
    const int rA  = (lane & 7) + ((lane >> 3) & 1) * 8;   // 0..15
    const int cAb = lane >> 4;                            // 0..1
    const int rB  = lane & 7;
    const int cBb = lane >> 3;                            // 0..3

    issue(0, 0);
    issue(1, 1);

    for (int kt = 0; kt < NKT; ++kt) {
        if (kt == NKT - 1) asm volatile("cp.async.wait_group 0;");
        else               asm volatile("cp.async.wait_group 1;");
        __syncthreads();

        const int s = kt % STAGES;
        const uint32_t abase = smem_base + s * 32768;
        const uint32_t bbase = abase + 16384;

#pragma unroll
        for (int kp = 0; kp < 2; ++kp) {
            uint32_t bq[4][4];
#pragma unroll
            for (int nf = 0; nf < 4; ++nf) {
                const int row = wn * 32 + nf * 8 + rB;
                const int c   = kp * 4 + cBb;
                ldsm4(bq[nf][0], bq[nf][1], bq[nf][2], bq[nf][3],
                      bbase + (uint32_t)(row * 8 + (c ^ (row & 7))) * 16);
            }
#pragma unroll
            for (int s2 = 0; s2 < 2; ++s2) {
                const int ks = kp * 2 + s2;
                uint32_t af[4][4];
#pragma unroll
                for (int mf = 0; mf < 4; ++mf) {
                    const int row = wm * 64 + mf * 16 + rA;
                    const int c   = ks * 2 + cAb;
                    ldsm4(af[mf][0], af[mf][1], af[mf][2], af[mf][3],
                          abase + (uint32_t)(row * 8 + (c ^ (row & 7))) * 16);
                }
#pragma unroll
                for (int mf = 0; mf < 4; ++mf)
#pragma unroll
                    for (int nf = 0; nf < 4; ++nf)
                        mma_tf32(acc[mf][nf], af[mf],
                                 bq[nf][2 * s2], bq[nf][2 * s2 + 1]);
            }
        }

        if (kt + 2 < NKT) issue(kt + 2, (kt + 2) % STAGES);
    }

    // ---- epilogue: bias + q-scale + store
    const float scale = (blockIdx.x < 4) ? SCALE_Q : 1.0f;
    const int gq = lane >> 2, tq = lane & 3;
#pragma unroll
    for (int n = 0; n < 4; ++n) {
        const int col = bn + wn * 32 + n * 8 + tq * 2;
        const float bx = bias_vec[col];
        const float by = bias_vec[col + 1];
#pragma unroll
        for (int m = 0; m < 4; ++m) {
            const int row0 = bm + wm * 64 + m * 16 + gq;
            float* o0 = &g_qkv[(size_t)row0 * THREE_D + col];
            *(float2*)o0 = make_float2((acc[m][n][0] + bx) * scale,
                                       (acc[m][n][1] + by) * scale);
            float* o1 = o0 + (size_t)8 * THREE_D;
            *(float2*)o1 = make_float2((acc[m][n][2] + bx) * scale,
                                       (acc[m][n][3] + by) * scale);
        }
    }
}

// ---------------------------------------------------------------------------
// Kernel 2: per (window, head) attention.  (unchanged)
// ---------------------------------------------------------------------------
__device__ __forceinline__ int region_id(int g) {
    return g < 56 ? 0 : (g < 60 ? 1 : 2);
}

__global__ __launch_bounds__(256)
void win_attn(const float* __restrict__ bias_table, float* __restrict__ out) {
    const int head = blockIdx.x;
    const int wdx  = blockIdx.y;
    const int n  = wdx >> 6;
    const int r  = wdx & 63;
    const int wh = r >> 3;
    const int ww = r & 7;

    __shared__ float Qs[64][32];
    __shared__ float Kt[32][64];
    __shared__ float Vs[64][32];
    __shared__ float Ps[64][68];
    __shared__ float bias_s[225];

    const int tid = threadIdx.x;

    for (int i2 = tid; i2 < 225; i2 += 256)
        bias_s[i2] = bias_table[i2 * N_HEAD + head];

#pragma unroll
    for (int pass = 0; pass < 2; ++pass) {
        int idx = tid + pass * 256;
        int row = idx >> 3;
        int c4  = (idx & 7) * 4;
        int tok = ((n * 64 + wh * 8 + (row >> 3)) * 64 + ww * 8 + (row & 7));
        const float* base = g_qkv + (size_t)tok * THREE_D + head * HEAD_DIM + c4;
        float4 qv = *(const float4*)(base);
        float4 kv = *(const float4*)(base + 512);
        float4 vv = *(const float4*)(base + 1024);
        *(float4*)&Qs[row][c4] = qv;
        Kt[c4 + 0][row] = kv.x; Kt[c4 + 1][row] = kv.y;
        Kt[c4 + 2][row] = kv.z; Kt[c4 + 3][row] = kv.w;
        *(float4*)&Vs[row][c4] = vv;
    }
    __syncthreads();

    const int ti = tid >> 4, tj = tid & 15;
    const int i0 = ti * 4, j0 = tj * 4;
    {
        float acc[4][4];
#pragma unroll
        for (int a = 0; a < 4; ++a)
#pragma unroll
            for (int c = 0; c < 4; ++c) acc[a][c] = 0.f;

#pragma unroll
        for (int kc = 0; kc < 4; ++kc) {
            float qreg[4][8];
#pragma unroll
            for (int a = 0; a < 4; ++a) {
                *(float4*)&qreg[a][0] = *(const float4*)&Qs[i0 + a][kc * 8];
                *(float4*)&qreg[a][4] = *(const float4*)&Qs[i0 + a][kc * 8 + 4];
            }
#pragma unroll
            for (int kk = 0; kk < 8; ++kk) {
                float4 kvv = *(const float4*)&Kt[kc * 8 + kk][j0];
#pragma unroll
                for (int a = 0; a < 4; ++a) {
                    float qe = qreg[a][kk];
                    acc[a][0] += qe * kvv.x;
                    acc[a][1] += qe * kvv.y;
                    acc[a][2] += qe * kvv.z;
                    acc[a][3] += qe * kvv.w;
                }
            }
        }

#pragma unroll
        for (int a = 0; a < 4; ++a) {
            const int i  = i0 + a;
            const int mi = region_id(wh * 8 + (i >> 3)) * 3 + region_id(ww * 8 + (i & 7));
#pragma unroll
            for (int c = 0; c < 4; ++c) {
                const int j  = j0 + c;
                const int d0 = (i >> 3) - (j >> 3) + 7;
                const int d1 = (i & 7)  - (j & 7)  + 7;
                float bm = bias_s[d0 * 15 + d1];
                const int mj = region_id(wh * 8 + (j >> 3)) * 3 + region_id(ww * 8 + (j & 7));
                if (mi != mj) bm -= 100.f;
                Ps[i][j] = acc[a][c] + bm;
            }
        }
    }
    __syncthreads();

    {
        const int lane = tid & 31, warp = tid >> 5;
#pragma unroll
        for (int rr = 0; rr < 8; ++rr) {
            const int row = warp * 8 + rr;
            float x0 = Ps[row][lane];
            float x1 = Ps[row][lane + 32];
            float m = fmaxf(x0, x1);
#pragma unroll
            for (int off = 16; off > 0; off >>= 1)
                m = fmaxf(m, __shfl_xor_sync(0xffffffffu, m, off));
            float e0 = __expf(x0 - m);
            float e1 = __expf(x1 - m);
            float s = e0 + e1;
#pragma unroll
            for (int off = 16; off > 0; off >>= 1)
                s += __shfl_xor_sync(0xffffffffu, s, off);
            const float inv = 1.0f / s;
            Ps[row][lane]      = e0 * inv;
            Ps[row][lane + 32] = e1 * inv;
        }
    }
    __syncthreads();

    {
        const int dd = tj * 2;
        float o[4][2];
#pragma unroll
        for (int a = 0; a < 4; ++a) { o[a][0] = 0.f; o[a][1] = 0.f; }

#pragma unroll
        for (int jc = 0; jc < 16; ++jc) {
            float pr[4][4];
#pragma unroll
            for (int a = 0; a < 4; ++a)
                *(float4*)&pr[a][0] = *(const float4*)&Ps[i0 + a][jc * 4];
            float2 vv[4];
#pragma unroll
            for (int u = 0; u < 4; ++u)
                vv[u] = *(const float2*)&Vs[jc * 4 + u][dd];
#pragma unroll
            for (int a = 0; a < 4; ++a)
#pragma unroll
                for (int u = 0; u < 4; ++u) {
                    o[a][0] += pr[a][u] * vv[u].x;
                    o[a][1] += pr[a][u] * vv[u].y;
                }
        }

#pragma unroll
        for (int a = 0; a < 4; ++a) {
            const int i   = i0 + a;
            const int tok = ((n * 64 + wh * 8 + (i >> 3)) * 64 + ww * 8 + (i & 7));
            float2* dst = (float2*)(out + (size_t)tok * D_MODEL + head * HEAD_DIM + dd);
            *dst = make_float2(o[a][0], o[a][1]);
        }
    }
}

// ---------------------------------------------------------------------------
extern "C" void kernel_launch(void* const* d_in, const int* in_sizes, int n_in,
                              void* d_out, int out_size) {
    const float* x  = (const float*)d_in[0];   // (8,64,64,512) f32
    const float* w  = (const float*)d_in[1];   // (1536,512)   f32
    const float* b  = (const float*)d_in[2];   // (1536,)      f32
    const float* bt = (const float*)d_in[3];   // (225,16)     f32
    float* out = (float*)d_out;                // (8,64,64,512) f32

    float* xr; cudaGetSymbolAddress((void**)&xr, g_xr);
    float* wr; cudaGetSymbolAddress((void**)&wr, g_wr);

    const int n4x = M_TOK * D_MODEL / 4;       // 4194304
    const int n4w = THREE_D * D_MODEL / 4;     // 196608
    round_tf32<<<(n4x + 255) / 256, 256>>>(x, xr, n4x);
    round_tf32<<<(n4w + 255) / 256, 256>>>(w, wr, n4w);

    cudaFuncSetAttribute(qkv_gemm_tc, cudaFuncAttributeMaxDynamicSharedMemorySize,
                         STAGES * 32768);
    dim3 g1(THREE_D / 128, M_TOK / 128);       // (12, 256)
    qkv_gemm_tc<<<g1, 256, STAGES * 32768>>>(xr, wr, b);

    dim3 g2(N_HEAD, 512);                      // head, window
    win_attn<<<g2, 256>>>(bt, out);
}

// round 5
// speedup vs baseline: 3.4141x; 1.1972x over previous
#include <cuda_runtime.h>
#include <cstdint>

#define D_MODEL   512
#define THREE_D   1536
#define M_TOK     32768      // 8 * 64 * 64 tokens
#define N_HEAD    16
#define HEAD_DIM  32
#define SCALE_Q   0.17677669529663689f   // 1/sqrt(32)
#define STAGES    3
#define NKT       16         // 512 / 32

// Device-global scratch (allocation-guard-safe)
__device__ float g_qkv[(size_t)M_TOK * THREE_D];          // 201 MB
__device__ float g_xr[(size_t)M_TOK * D_MODEL];           // 64 MB  tf32-rounded x
__device__ float g_wr[(size_t)THREE_D * D_MODEL];         // 3 MB   tf32-rounded w

__device__ __forceinline__ uint32_t f2tf32(float f) {
    uint32_t u;
    asm("cvt.rna.tf32.f32 %0, %1;" : "=r"(u) : "f"(f));
    return u;
}

__device__ __forceinline__ void split_tf32(float v, uint32_t& hi, uint32_t& lo) {
    hi = f2tf32(v);
    lo = f2tf32(v - __uint_as_float(hi));
}

__device__ __forceinline__ void ldsm4(uint32_t& r0, uint32_t& r1, uint32_t& r2,
                                      uint32_t& r3, uint32_t addr) {
    asm volatile("ldmatrix.sync.aligned.m8n8.x4.shared.b16 {%0,%1,%2,%3}, [%4];"
                 : "=r"(r0), "=r"(r1), "=r"(r2), "=r"(r3) : "r"(addr));
}

__device__ __forceinline__ void mma_tf32(float* c, const uint32_t* a,
                                         uint32_t b0, uint32_t b1) {
    asm volatile(
        "mma.sync.aligned.m16n8k8.row.col.f32.tf32.tf32.f32 "
        "{%0,%1,%2,%3}, {%4,%5,%6,%7}, {%8,%9}, {%0,%1,%2,%3};\n"
        : "+f"(c[0]), "+f"(c[1]), "+f"(c[2]), "+f"(c[3])
        : "r"(a[0]), "r"(a[1]), "r"(a[2]), "r"(a[3]), "r"(b0), "r"(b1));
}

// ---------------------------------------------------------------------------
// Pre-pass: round f32 -> tf32 (stored as f32 bits with low mantissa zeroed)
// ---------------------------------------------------------------------------
__global__ void round_tf32(const float* __restrict__ in, float* __restrict__ out, int n4) {
    int i = blockIdx.x * 256 + threadIdx.x;
    if (i >= n4) return;
    float4 v = ((const float4*)in)[i];
    uint4 o;
    o.x = f2tf32(v.x); o.y = f2tf32(v.y); o.z = f2tf32(v.z); o.w = f2tf32(v.w);
    ((uint4*)out)[i] = o;
}

// ---------------------------------------------------------------------------
// Kernel 1: qkv = xr @ wr^T + b  (tf32 mma, cp.async 3-stage pipeline)
// (unchanged from round 4)
// ---------------------------------------------------------------------------
__global__ __launch_bounds__(256, 2)
void qkv_gemm_tc(const float* __restrict__ xr,
                 const float* __restrict__ wr,
                 const float* __restrict__ bias_vec) {
    extern __shared__ uint32_t smem[];   // STAGES * (A 16KB + B 16KB)
    const uint32_t smem_base = (uint32_t)__cvta_generic_to_shared(smem);

    const int tid  = threadIdx.x;
    const int lane = tid & 31, warp = tid >> 5;
    const int wm = warp >> 2, wn = warp & 3;        // 2 x 4 warp grid
    const int bm = blockIdx.y * 128, bn = blockIdx.x * 128;

    const float* aptr[4];
    const float* bptr[4];
    uint32_t swz[4];
#pragma unroll
    for (int i = 0; i < 4; ++i) {
        const int id  = i * 256 + tid;              // 0..1023
        const int row = id >> 3, c = id & 7;
        swz[i]  = (uint32_t)(row * 8 + (c ^ (row & 7))) * 16;
        aptr[i] = xr + (size_t)(bm + row) * D_MODEL + c * 4;
        bptr[i] = wr + (size_t)(bn + row) * D_MODEL + c * 4;
    }

    auto issue = [&](int kt, int s) {
        const uint32_t ab = smem_base + s * 32768;
        const uint32_t bb = ab + 16384;
#pragma unroll
        for (int i = 0; i < 4; ++i) {
            asm volatile("cp.async.cg.shared.global [%0], [%1], 16;"
                         :: "r"(ab + swz[i]), "l"(aptr[i] + kt * 32));
            asm volatile("cp.async.cg.shared.global [%0], [%1], 16;"
                         :: "r"(bb + swz[i]), "l"(bptr[i] + kt * 32));
        }
        asm volatile("cp.async.commit_group;");
    };

    float acc[4][4][4];
#pragma unroll
    for (int m = 0; m < 4; ++m)
#pragma unroll
        for (int n = 0; n < 4; ++n)
#pragma unroll
            for (int q = 0; q < 4; ++q) acc[m][n][q] = 0.f;

    const int rA  = (lane & 7) + ((lane >> 3) & 1) * 8;   // 0..15
    const int cAb = lane >> 4;                            // 0..1
    const int rB  = lane & 7;
    const int cBb = lane >> 3;                            // 0..3

    issue(0, 0);
    issue(1, 1);

    for (int kt = 0; kt < NKT; ++kt) {
        if (kt == NKT - 1) asm volatile("cp.async.wait_group 0;");
        else               asm volatile("cp.async.wait_group 1;");
        __syncthreads();

        const int s = kt % STAGES;
        const uint32_t abase = smem_base + s * 32768;
        const uint32_t bbase = abase + 16384;

#pragma unroll
        for (int kp = 0; kp < 2; ++kp) {
            uint32_t bq[4][4];
#pragma unroll
            for (int nf = 0; nf < 4; ++nf) {
                const int row = wn * 32 + nf * 8 + rB;
                const int c   = kp * 4 + cBb;
                ldsm4(bq[nf][0], bq[nf][1], bq[nf][2], bq[nf][3],
                      bbase + (uint32_t)(row * 8 + (c ^ (row & 7))) * 16);
            }
#pragma unroll
            for (int s2 = 0; s2 < 2; ++s2) {
                const int ks = kp * 2 + s2;
                uint32_t af[4][4];
#pragma unroll
                for (int mf = 0; mf < 4; ++mf) {
                    const int row = wm * 64 + mf * 16 + rA;
                    const int c   = ks * 2 + cAb;
                    ldsm4(af[mf][0], af[mf][1], af[mf][2], af[mf][3],
                          abase + (uint32_t)(row * 8 + (c ^ (row & 7))) * 16);
                }
#pragma unroll
                for (int mf = 0; mf < 4; ++mf)
#pragma unroll
                    for (int nf = 0; nf < 4; ++nf)
                        mma_tf32(acc[mf][nf], af[mf],
                                 bq[nf][2 * s2], bq[nf][2 * s2 + 1]);
            }
        }

        if (kt + 2 < NKT) issue(kt + 2, (kt + 2) % STAGES);
    }

    const float scale = (blockIdx.x < 4) ? SCALE_Q : 1.0f;
    const int gq = lane >> 2, tq = lane & 3;
#pragma unroll
    for (int n = 0; n < 4; ++n) {
        const int col = bn + wn * 32 + n * 8 + tq * 2;
        const float bx = bias_vec[col];
        const float by = bias_vec[col + 1];
#pragma unroll
        for (int m = 0; m < 4; ++m) {
            const int row0 = bm + wm * 64 + m * 16 + gq;
            float* o0 = &g_qkv[(size_t)row0 * THREE_D + col];
            *(float2*)o0 = make_float2((acc[m][n][0] + bx) * scale,
                                       (acc[m][n][1] + by) * scale);
            float* o1 = o0 + (size_t)8 * THREE_D;
            *(float2*)o1 = make_float2((acc[m][n][2] + bx) * scale,
                                       (acc[m][n][3] + by) * scale);
        }
    }
}

// ---------------------------------------------------------------------------
// Kernel 2: per (window, head) attention via split-tf32 mma (3xTF32).
// 128 threads / 4 warps; warp w owns rows 16w..16w+15.
// Fragment loads are direct LDS with conflict-free strides:
//   Q/K stride 36 floats, V stride 40, P stride 68.
// ---------------------------------------------------------------------------
__device__ __forceinline__ int region_id(int g) {
    return g < 56 ? 0 : (g < 60 ? 1 : 2);
}

__global__ __launch_bounds__(128)
void win_attn_mma(const float* __restrict__ bias_table, float* __restrict__ out) {
    const int head = blockIdx.x;
    const int wdx  = blockIdx.y;
    const int n  = wdx >> 6;
    const int rr = wdx & 63;
    const int wh = rr >> 3;
    const int ww = rr & 7;

    __shared__ float Qs[64 * 36];
    __shared__ float Ks[64 * 36];
    __shared__ float Vs[64 * 40];
    __shared__ float Ps[64 * 68];
    __shared__ float bias_s[228];

    const int tid  = threadIdx.x;
    const int lane = tid & 31, warp = tid >> 5;
    const int qr = lane >> 2, qc = lane & 3;   // quad row / col within fragment

    for (int i = tid; i < 225; i += 128)
        bias_s[i] = bias_table[i * N_HEAD + head];

    // ---- load Q, K, V (64x32 each) from g_qkv
#pragma unroll
    for (int pass = 0; pass < 4; ++pass) {
        const int idx = pass * 128 + tid;       // 0..511
        const int row = idx >> 3;
        const int c4  = (idx & 7) * 4;
        const int tok = ((n * 64 + wh * 8 + (row >> 3)) * 64 + ww * 8 + (row & 7));
        const float* base = g_qkv + (size_t)tok * THREE_D + head * HEAD_DIM + c4;
        *(float4*)&Qs[row * 36 + c4] = *(const float4*)(base);
        *(float4*)&Ks[row * 36 + c4] = *(const float4*)(base + 512);
        *(float4*)&Vs[row * 40 + c4] = *(const float4*)(base + 1024);
    }
    __syncthreads();

    const int m0 = warp * 16;

    // ---- phase 1: S = Q K^T  (per warp: 16x64, k=32)
    float acc[8][4];
#pragma unroll
    for (int nf = 0; nf < 8; ++nf)
#pragma unroll
        for (int q = 0; q < 4; ++q) acc[nf][q] = 0.f;

#pragma unroll
    for (int ks = 0; ks < 4; ++ks) {
        const int k0 = ks * 8;
        float a[4];
        a[0] = Qs[(m0 + qr)     * 36 + k0 + qc];
        a[1] = Qs[(m0 + qr + 8) * 36 + k0 + qc];
        a[2] = Qs[(m0 + qr)     * 36 + k0 + qc + 4];
        a[3] = Qs[(m0 + qr + 8) * 36 + k0 + qc + 4];
        uint32_t ahi[4], alo[4];
#pragma unroll
        for (int q = 0; q < 4; ++q) split_tf32(a[q], ahi[q], alo[q]);

#pragma unroll
        for (int nf = 0; nf < 8; ++nf) {
            const float b0 = Ks[(nf * 8 + qr) * 36 + k0 + qc];
            const float b1 = Ks[(nf * 8 + qr) * 36 + k0 + qc + 4];
            uint32_t bh0, bl0, bh1, bl1;
            split_tf32(b0, bh0, bl0);
            split_tf32(b1, bh1, bl1);
            mma_tf32(acc[nf], ahi, bh0, bh1);
            mma_tf32(acc[nf], ahi, bl0, bl1);
            mma_tf32(acc[nf], alo, bh0, bh1);
        }
    }

    // ---- phase 2: bias + mask + row softmax in C-fragment registers
#pragma unroll
    for (int h = 0; h < 2; ++h) {
        const int i  = m0 + qr + 8 * h;
        const int ih = i >> 3, iw = i & 7;
        const int mi = region_id(wh * 8 + ih) * 3 + region_id(ww * 8 + iw);

        float vals[16];
#pragma unroll
        for (int nf = 0; nf < 8; ++nf) {
            const int d0row = (ih - nf + 7) * 15;
            const int regh3 = region_id(wh * 8 + nf) * 3;
#pragma unroll
            for (int e = 0; e < 2; ++e) {
                const int j = 2 * qc + e;                  // j & 7
                float v = acc[nf][2 * h + e] + bias_s[d0row + (iw - j + 7)];
                if (mi != regh3 + region_id(ww * 8 + j)) v -= 100.f;
                vals[nf * 2 + e] = v;
            }
        }
        float mx = vals[0];
#pragma unroll
        for (int q = 1; q < 16; ++q) mx = fmaxf(mx, vals[q]);
        mx = fmaxf(mx, __shfl_xor_sync(0xffffffffu, mx, 1));
        mx = fmaxf(mx, __shfl_xor_sync(0xffffffffu, mx, 2));
        float sum = 0.f;
#pragma unroll
        for (int q = 0; q < 16; ++q) { vals[q] = __expf(vals[q] - mx); sum += vals[q]; }
        sum += __shfl_xor_sync(0xffffffffu, sum, 1);
        sum += __shfl_xor_sync(0xffffffffu, sum, 2);
        const float inv = 1.0f / sum;
#pragma unroll
        for (int nf = 0; nf < 8; ++nf)
            *(float2*)&Ps[i * 68 + nf * 8 + 2 * qc] =
                make_float2(vals[nf * 2] * inv, vals[nf * 2 + 1] * inv);
    }
    __syncthreads();

    // ---- phase 3: O = P V  (per warp: 16x32, k=64)
    float oacc[4][4];
#pragma unroll
    for (int nf = 0; nf < 4; ++nf)
#pragma unroll
        for (int q = 0; q < 4; ++q) oacc[nf][q] = 0.f;

#pragma unroll
    for (int ks = 0; ks < 8; ++ks) {
        const int k0 = ks * 8;
        float a[4];
        a[0] = Ps[(m0 + qr)     * 68 + k0 + qc];
        a[1] = Ps[(m0 + qr + 8) * 68 + k0 + qc];
        a[2] = Ps[(m0 + qr)     * 68 + k0 + qc + 4];
        a[3] = Ps[(m0 + qr + 8) * 68 + k0 + qc + 4];
        uint32_t ahi[4], alo[4];
#pragma unroll
        for (int q = 0; q < 4; ++q) split_tf32(a[q], ahi[q], alo[q]);

#pragma unroll
        for (int nf = 0; nf < 4; ++nf) {
            const float b0 = Vs[(k0 + qc)     * 40 + nf * 8 + qr];
            const float b1 = Vs[(k0 + qc + 4) * 40 + nf * 8 + qr];
            uint32_t bh0, bl0, bh1, bl1;
            split_tf32(b0, bh0, bl0);
            split_tf32(b1, bh1, bl1);
            mma_tf32(oacc[nf], ahi, bh0, bh1);
            mma_tf32(oacc[nf], ahi, bl0, bl1);
            mma_tf32(oacc[nf], alo, bh0, bh1);
        }
    }

    // ---- write output in (n,H,W,c) layout
#pragma unroll
    for (int nf = 0; nf < 4; ++nf)
#pragma unroll
        for (int h = 0; h < 2; ++h) {
            const int i   = m0 + qr + 8 * h;
            const int tok = ((n * 64 + wh * 8 + (i >> 3)) * 64 + ww * 8 + (i & 7));
            float2* dst = (float2*)(out + (size_t)tok * D_MODEL + head * HEAD_DIM
                                    + nf * 8 + 2 * qc);
            *dst = make_float2(oacc[nf][2 * h], oacc[nf][2 * h + 1]);
        }
}

// ---------------------------------------------------------------------------
extern "C" void kernel_launch(void* const* d_in, const int* in_sizes, int n_in,
                              void* d_out, int out_size) {
    const float* x  = (const float*)d_in[0];   // (8,64,64,512) f32
    const float* w  = (const float*)d_in[1];   // (1536,512)   f32
    const float* b  = (const float*)d_in[2];   // (1536,)      f32
    const float* bt = (const float*)d_in[3];   // (225,16)     f32
    float* out = (float*)d_out;                // (8,64,64,512) f32

    float* xr; cudaGetSymbolAddress((void**)&xr, g_xr);
    float* wr; cudaGetSymbolAddress((void**)&wr, g_wr);

    const int n4x = M_TOK * D_MODEL / 4;       // 4194304
    const int n4w = THREE_D * D_MODEL / 4;     // 196608
    round_tf32<<<(n4x + 255) / 256, 256>>>(x, xr, n4x);
    round_tf32<<<(n4w + 255) / 256, 256>>>(w, wr, n4w);

    cudaFuncSetAttribute(qkv_gemm_tc, cudaFuncAttributeMaxDynamicSharedMemorySize,
                         STAGES * 32768);
    dim3 g1(THREE_D / 128, M_TOK / 128);       // (12, 256)
    qkv_gemm_tc<<<g1, 256, STAGES * 32768>>>(xr, wr, b);

    dim3 g2(N_HEAD, 512);                      // head, window
    win_attn_mma<<<g2, 128>>>(bt, out);
}

// round 7
// speedup vs baseline: 4.6290x; 1.3559x over previous
#include <cuda_runtime.h>
#include <cuda_fp16.h>
#include <cstdint>

#define D_MODEL   512
#define THREE_D   1536
#define M_TOK     32768      // 8 * 64 * 64 tokens
#define N_HEAD    16
#define HEAD_DIM  32
#define SCALE_Q   0.17677669529663689f   // 1/sqrt(32)
#define STAGES    3
#define NKT       16         // 512 / 32 halves per k-tile
#define ROWB      80         // smem row stride bytes (32 halves + 16B pad)
#define TILEB     (128 * ROWB)          // 10240 per operand tile
#define STAGEB    (2 * TILEB)           // 20480 per stage

// Device-global scratch (allocation-guard-safe)
__device__ float  g_qkv[(size_t)M_TOK * THREE_D];        // 201 MB
__device__ __half g_xh[(size_t)M_TOK * D_MODEL];         // 32 MB  fp16 x
__device__ __half g_wh[(size_t)THREE_D * D_MODEL];       // 1.5 MB fp16 w

__device__ __forceinline__ uint32_t f2tf32(float f) {
    uint32_t u;
    asm("cvt.rna.tf32.f32 %0, %1;" : "=r"(u) : "f"(f));
    return u;
}

__device__ __forceinline__ void split_tf32(float v, uint32_t& hi, uint32_t& lo) {
    hi = f2tf32(v);
    lo = f2tf32(v - __uint_as_float(hi));
}

__device__ __forceinline__ void mma_tf32(float* c, const uint32_t* a,
                                         uint32_t b0, uint32_t b1) {
    asm volatile(
        "mma.sync.aligned.m16n8k8.row.col.f32.tf32.tf32.f32 "
        "{%0,%1,%2,%3}, {%4,%5,%6,%7}, {%8,%9}, {%0,%1,%2,%3};\n"
        : "+f"(c[0]), "+f"(c[1]), "+f"(c[2]), "+f"(c[3])
        : "r"(a[0]), "r"(a[1]), "r"(a[2]), "r"(a[3]), "r"(b0), "r"(b1));
}

__device__ __forceinline__ void mma_f16(float* c, const uint32_t* a,
                                        uint32_t b0, uint32_t b1) {
    asm volatile(
        "mma.sync.aligned.m16n8k16.row.col.f32.f16.f16.f32 "
        "{%0,%1,%2,%3}, {%4,%5,%6,%7}, {%8,%9}, {%0,%1,%2,%3};\n"
        : "+f"(c[0]), "+f"(c[1]), "+f"(c[2]), "+f"(c[3])
        : "r"(a[0]), "r"(a[1]), "r"(a[2]), "r"(a[3]), "r"(b0), "r"(b1));
}

__device__ __forceinline__ void ldsm4(uint32_t& r0, uint32_t& r1, uint32_t& r2,
                                      uint32_t& r3, uint32_t addr) {
    asm volatile("ldmatrix.sync.aligned.m8n8.x4.shared.b16 {%0,%1,%2,%3}, [%4];"
                 : "=r"(r0), "=r"(r1), "=r"(r2), "=r"(r3) : "r"(addr));
}

__device__ __forceinline__ void ldsm2(uint32_t& r0, uint32_t& r1, uint32_t addr) {
    asm volatile("ldmatrix.sync.aligned.m8n8.x2.shared.b16 {%0,%1}, [%2];"
                 : "=r"(r0), "=r"(r1) : "r"(addr));
}

// ---------------------------------------------------------------------------
// Pre-pass: f32 -> f16 (RN). Each thread converts 8 values (16B store).
// ---------------------------------------------------------------------------
__global__ void to_half(const float* __restrict__ in, __half* __restrict__ out, int n8) {
    int i = blockIdx.x * 256 + threadIdx.x;
    if (i >= n8) return;
    float4 v0 = ((const float4*)in)[2 * i];
    float4 v1 = ((const float4*)in)[2 * i + 1];
    __half2 h[4];
    h[0] = __floats2half2_rn(v0.x, v0.y);
    h[1] = __floats2half2_rn(v0.z, v0.w);
    h[2] = __floats2half2_rn(v1.x, v1.y);
    h[3] = __floats2half2_rn(v1.z, v1.w);
    ((uint4*)out)[i] = *(uint4*)h;
}

// ---------------------------------------------------------------------------
// Kernel 1: qkv = xh @ wh^T + b  (fp16 mma m16n8k16, cp.async 3-stage)
// BM=BN=128, BK=32 halves. 8 warps as 2(m) x 4(n); warp tile 64x32.
// SMEM rows: 32 halves + 16B pad (stride 80B) -> (5r+c) mod 8 bijection
// makes ldmatrix phases conflict-free.
// ---------------------------------------------------------------------------
__global__ __launch_bounds__(256, 2)
void qkv_gemm_f16(const __half* __restrict__ xh,
                  const __half* __restrict__ wh,
                  const float* __restrict__ bias_vec) {
    extern __shared__ char smem[];   // STAGES * (A 10240 + B 10240)
    const uint32_t smem_base = (uint32_t)__cvta_generic_to_shared(smem);

    const int tid  = threadIdx.x;
    const int lane = tid & 31, warp = tid >> 5;
    const int wm = warp >> 2, wn = warp & 3;        // 2 x 4 warp grid
    const int bm = blockIdx.y * 128, bn = blockIdx.x * 128;

    // loader: 2 A-granules + 2 B-granules of 16B (8 halves) per thread
    const __half* aptr[2];
    const __half* bptr[2];
    uint32_t soff[2];
#pragma unroll
    for (int i = 0; i < 2; ++i) {
        const int id  = i * 256 + tid;              // 0..511
        const int row = id >> 2, c = id & 3;
        soff[i] = (uint32_t)(row * ROWB + c * 16);
        aptr[i] = xh + (size_t)(bm + row) * D_MODEL + c * 8;
        bptr[i] = wh + (size_t)(bn + row) * D_MODEL + c * 8;
    }

    auto issue = [&](int kt, int s) {
        const uint32_t ab = smem_base + s * STAGEB;
        const uint32_t bb = ab + TILEB;
#pragma unroll
        for (int i = 0; i < 2; ++i) {
            asm volatile("cp.async.cg.shared.global [%0], [%1], 16;"
                         :: "r"(ab + soff[i]), "l"(aptr[i] + kt * 32));
            asm volatile("cp.async.cg.shared.global [%0], [%1], 16;"
                         :: "r"(bb + soff[i]), "l"(bptr[i] + kt * 32));
        }
        asm volatile("cp.async.commit_group;");
    };

    float acc[4][4][4];
#pragma unroll
    for (int m = 0; m < 4; ++m)
#pragma unroll
        for (int n = 0; n < 4; ++n)
#pragma unroll
            for (int q = 0; q < 4; ++q) acc[m][n][q] = 0.f;

    // ldmatrix per-lane addressing offsets
    const int laneR8 = lane & 7;
    const int aRow   = laneR8 + ((lane >> 3) & 1) * 8;   // + mat&1 * 8
    const int aChunk = lane >> 4;                        // mat>>1
    const int bRow   = laneR8;                           // lanes 0..15 used
    const int bChunk = (lane >> 3) & 1;

    issue(0, 0);
    issue(1, 1);

    for (int kt = 0; kt < NKT; ++kt) {
        if (kt == NKT - 1) asm volatile("cp.async.wait_group 0;");
        else               asm volatile("cp.async.wait_group 1;");
        __syncthreads();

        const int s = kt % STAGES;
        const uint32_t abase = smem_base + s * STAGEB;
        const uint32_t bbase = abase + TILEB;

#pragma unroll
        for (int ks = 0; ks < 2; ++ks) {            // two k16 steps per BK=32
            uint32_t af[4][4];
#pragma unroll
            for (int mf = 0; mf < 4; ++mf) {
                const int row = wm * 64 + mf * 16 + aRow;
                ldsm4(af[mf][0], af[mf][1], af[mf][2], af[mf][3],
                      abase + (uint32_t)(row * ROWB + (ks * 2 + aChunk) * 16));
            }
            uint32_t bf[4][2];
#pragma unroll
            for (int nf = 0; nf < 4; ++nf) {
                const int row = wn * 32 + nf * 8 + bRow;
                ldsm2(bf[nf][0], bf[nf][1],
                      bbase + (uint32_t)(row * ROWB + (ks * 2 + bChunk) * 16));
            }
#pragma unroll
            for (int mf = 0; mf < 4; ++mf)
#pragma unroll
                for (int nf = 0; nf < 4; ++nf)
                    mma_f16(acc[mf][nf], af[mf], bf[nf][0], bf[nf][1]);
        }

        if (kt + 2 < NKT) issue(kt + 2, (kt + 2) % STAGES);
    }

    // ---- epilogue: bias + q-scale + store (f32)
    const float scale = (blockIdx.x < 4) ? SCALE_Q : 1.0f;
    const int gq = lane >> 2, tq = lane & 3;
#pragma unroll
    for (int n = 0; n < 4; ++n) {
        const int col = bn + wn * 32 + n * 8 + tq * 2;
        const float bx = bias_vec[col];
        const float by = bias_vec[col + 1];
#pragma unroll
        for (int m = 0; m < 4; ++m) {
            const int row0 = bm + wm * 64 + m * 16 + gq;
            float* o0 = &g_qkv[(size_t)row0 * THREE_D + col];
            *(float2*)o0 = make_float2((acc[m][n][0] + bx) * scale,
                                       (acc[m][n][1] + by) * scale);
            float* o1 = o0 + (size_t)8 * THREE_D;
            *(float2*)o1 = make_float2((acc[m][n][2] + bx) * scale,
                                       (acc[m][n][3] + by) * scale);
        }
    }
}

// ---------------------------------------------------------------------------
// Kernel 2: per (window, head) attention via split-tf32 mma (unchanged R5).
// ---------------------------------------------------------------------------
__device__ __forceinline__ int region_id(int g) {
    return g < 56 ? 0 : (g < 60 ? 1 : 2);
}

__global__ __launch_bounds__(128)
void win_attn_mma(const float* __restrict__ bias_table, float* __restrict__ out) {
    const int head = blockIdx.x;
    const int wdx  = blockIdx.y;
    const int n  = wdx >> 6;
    const int rr = wdx & 63;
    const int wh = rr >> 3;
    const int ww = rr & 7;

    __shared__ float Qs[64 * 36];
    __shared__ float Ks[64 * 36];
    __shared__ float Vs[64 * 40];
    __shared__ float Ps[64 * 68];
    __shared__ float bias_s[228];

    const int tid  = threadIdx.x;
    const int lane = tid & 31, warp = tid >> 5;
    const int qr = lane >> 2, qc = lane & 3;

    for (int i = tid; i < 225; i += 128)
        bias_s[i] = bias_table[i * N_HEAD + head];

#pragma unroll
    for (int pass = 0; pass < 4; ++pass) {
        const int idx = pass * 128 + tid;
        const int row = idx >> 3;
        const int c4  = (idx & 7) * 4;
        const int tok = ((n * 64 + wh * 8 + (row >> 3)) * 64 + ww * 8 + (row & 7));
        const float* base = g_qkv + (size_t)tok * THREE_D + head * HEAD_DIM + c4;
        *(float4*)&Qs[row * 36 + c4] = *(const float4*)(base);
        *(float4*)&Ks[row * 36 + c4] = *(const float4*)(base + 512);
        *(float4*)&Vs[row * 40 + c4] = *(const float4*)(base + 1024);
    }
    __syncthreads();

    const int m0 = warp * 16;

    float acc[8][4];
#pragma unroll
    for (int nf = 0; nf < 8; ++nf)
#pragma unroll
        for (int q = 0; q < 4; ++q) acc[nf][q] = 0.f;

#pragma unroll
    for (int ks = 0; ks < 4; ++ks) {
        const int k0 = ks * 8;
        float a[4];
        a[0] = Qs[(m0 + qr)     * 36 + k0 + qc];
        a[1] = Qs[(m0 + qr + 8) * 36 + k0 + qc];
        a[2] = Qs[(m0 + qr)     * 36 + k0 + qc + 4];
        a[3] = Qs[(m0 + qr + 8) * 36 + k0 + qc + 4];
        uint32_t ahi[4], alo[4];
#pragma unroll
        for (int q = 0; q < 4; ++q) split_tf32(a[q], ahi[q], alo[q]);

#pragma unroll
        for (int nf = 0; nf < 8; ++nf) {
            const float b0 = Ks[(nf * 8 + qr) * 36 + k0 + qc];
            const float b1 = Ks[(nf * 8 + qr) * 36 + k0 + qc + 4];
            uint32_t bh0, bl0, bh1, bl1;
            split_tf32(b0, bh0, bl0);
            split_tf32(b1, bh1, bl1);
            mma_tf32(acc[nf], ahi, bh0, bh1);
            mma_tf32(acc[nf], ahi, bl0, bl1);
            mma_tf32(acc[nf], alo, bh0, bh1);
        }
    }

#pragma unroll
    for (int h = 0; h < 2; ++h) {
        const int i  = m0 + qr + 8 * h;
        const int ih = i >> 3, iw = i & 7;
        const int mi = region_id(wh * 8 + ih) * 3 + region_id(ww * 8 + iw);

        float vals[16];
#pragma unroll
        for (int nf = 0; nf < 8; ++nf) {
            const int d0row = (ih - nf + 7) * 15;
            const int regh3 = region_id(wh * 8 + nf) * 3;
#pragma unroll
            for (int e = 0; e < 2; ++e) {
                const int j = 2 * qc + e;
                float v = acc[nf][2 * h + e] + bias_s[d0row + (iw - j + 7)];
                if (mi != regh3 + region_id(ww * 8 + j)) v -= 100.f;
                vals[nf * 2 + e] = v;
            }
        }
        float mx = vals[0];
#pragma unroll
        for (int q = 1; q < 16; ++q) mx = fmaxf(mx, vals[q]);
        mx = fmaxf(mx, __shfl_xor_sync(0xffffffffu, mx, 1));
        mx = fmaxf(mx, __shfl_xor_sync(0xffffffffu, mx, 2));
        float sum = 0.f;
#pragma unroll
        for (int q = 0; q < 16; ++q) { vals[q] = __expf(vals[q] - mx); sum += vals[q]; }
        sum += __shfl_xor_sync(0xffffffffu, sum, 1);
        sum += __shfl_xor_sync(0xffffffffu, sum, 2);
        const float inv = 1.0f / sum;
#pragma unroll
        for (int nf = 0; nf < 8; ++nf)
            *(float2*)&Ps[i * 68 + nf * 8 + 2 * qc] =
                make_float2(vals[nf * 2] * inv, vals[nf * 2 + 1] * inv);
    }
    __syncthreads();

    float oacc[4][4];
#pragma unroll
    for (int nf = 0; nf < 4; ++nf)
#pragma unroll
        for (int q = 0; q < 4; ++q) oacc[nf][q] = 0.f;

#pragma unroll
    for (int ks = 0; ks < 8; ++ks) {
        const int k0 = ks * 8;
        float a[4];
        a[0] = Ps[(m0 + qr)     * 68 + k0 + qc];
        a[1] = Ps[(m0 + qr + 8) * 68 + k0 + qc];
        a[2] = Ps[(m0 + qr)     * 68 + k0 + qc + 4];
        a[3] = Ps[(m0 + qr + 8) * 68 + k0 + qc + 4];
        uint32_t ahi[4], alo[4];
#pragma unroll
        for (int q = 0; q < 4; ++q) split_tf32(a[q], ahi[q], alo[q]);

#pragma unroll
        for (int nf = 0; nf < 4; ++nf) {
            const float b0 = Vs[(k0 + qc)     * 40 + nf * 8 + qr];
            const float b1 = Vs[(k0 + qc + 4) * 40 + nf * 8 + qr];
            uint32_t bh0, bl0, bh1, bl1;
            split_tf32(b0, bh0, bl0);
            split_tf32(b1, bh1, bl1);
            mma_tf32(oacc[nf], ahi, bh0, bh1);
            mma_tf32(oacc[nf], ahi, bl0, bl1);
            mma_tf32(oacc[nf], alo, bh0, bh1);
        }
    }

#pragma unroll
    for (int nf = 0; nf < 4; ++nf)
#pragma unroll
        for (int h = 0; h < 2; ++h) {
            const int i   = m0 + qr + 8 * h;
            const int tok = ((n * 64 + wh * 8 + (i >> 3)) * 64 + ww * 8 + (i & 7));
            float2* dst = (float2*)(out + (size_t)tok * D_MODEL + head * HEAD_DIM
                                    + nf * 8 + 2 * qc);
            *dst = make_float2(oacc[nf][2 * h], oacc[nf][2 * h + 1]);
        }
}

// ---------------------------------------------------------------------------
extern "C" void kernel_launch(void* const* d_in, const int* in_sizes, int n_in,
                              void* d_out, int out_size) {
    const float* x  = (const float*)d_in[0];   // (8,64,64,512) f32
    const float* w  = (const float*)d_in[1];   // (1536,512)   f32
    const float* b  = (const float*)d_in[2];   // (1536,)      f32
    const float* bt = (const float*)d_in[3];   // (225,16)     f32
    float* out = (float*)d_out;                // (8,64,64,512) f32

    __half* xh; cudaGetSymbolAddress((void**)&xh, g_xh);
    __half* wh; cudaGetSymbolAddress((void**)&wh, g_wh);

    const int n8x = M_TOK * D_MODEL / 8;       // 2097152
    const int n8w = THREE_D * D_MODEL / 8;     // 98304
    to_half<<<(n8x + 255) / 256, 256>>>(x, xh, n8x);
    to_half<<<(n8w + 255) / 256, 256>>>(w, wh, n8w);

    cudaFuncSetAttribute(qkv_gemm_f16, cudaFuncAttributeMaxDynamicSharedMemorySize,
                         STAGES * STAGEB);
    dim3 g1(THREE_D / 128, M_TOK / 128);       // (12, 256)
    qkv_gemm_f16<<<g1, 256, STAGES * STAGEB>>>(xh, wh, b);

    dim3 g2(N_HEAD, 512);                      // head, window
    win_attn_mma<<<g2, 128>>>(bt, out);
}

// round 8
// speedup vs baseline: 4.7844x; 1.0336x over previous
#include <cuda_runtime.h>
#include <cuda_fp16.h>
#include <cstdint>

#define D_MODEL   512
#define THREE_D   1536
#define M_TOK     32768      // 8 * 64 * 64 tokens
#define N_HEAD    16
#define HEAD_DIM  32
#define SCALE_Q   0.17677669529663689f   // 1/sqrt(32)
#define STAGES    3
#define NKT       16         // 512 / 32 halves per k-tile
#define ROWB      80         // smem row stride bytes (32 halves + 16B pad)
// GEMM tiles: BM=256, BN=128, 512 threads
#define ATILEB    (256 * ROWB)          // 20480
#define BTILEB    (128 * ROWB)          // 10240
#define STAGEB    (ATILEB + BTILEB)     // 30720

// Device-global scratch (allocation-guard-safe)
__device__ float  g_qkv[(size_t)M_TOK * THREE_D];        // 201 MB
__device__ __half g_xh[(size_t)M_TOK * D_MODEL];         // 32 MB  fp16 x
__device__ __half g_wh[(size_t)THREE_D * D_MODEL];       // 1.5 MB fp16 w

__device__ __forceinline__ void mma_f16(float* c, const uint32_t* a,
                                        uint32_t b0, uint32_t b1) {
    asm volatile(
        "mma.sync.aligned.m16n8k16.row.col.f32.f16.f16.f32 "
        "{%0,%1,%2,%3}, {%4,%5,%6,%7}, {%8,%9}, {%0,%1,%2,%3};\n"
        : "+f"(c[0]), "+f"(c[1]), "+f"(c[2]), "+f"(c[3])
        : "r"(a[0]), "r"(a[1]), "r"(a[2]), "r"(a[3]), "r"(b0), "r"(b1));
}

__device__ __forceinline__ void ldsm4(uint32_t& r0, uint32_t& r1, uint32_t& r2,
                                      uint32_t& r3, uint32_t addr) {
    asm volatile("ldmatrix.sync.aligned.m8n8.x4.shared.b16 {%0,%1,%2,%3}, [%4];"
                 : "=r"(r0), "=r"(r1), "=r"(r2), "=r"(r3) : "r"(addr));
}

__device__ __forceinline__ void ldsm2(uint32_t& r0, uint32_t& r1, uint32_t addr) {
    asm volatile("ldmatrix.sync.aligned.m8n8.x2.shared.b16 {%0,%1}, [%2];"
                 : "=r"(r0), "=r"(r1) : "r"(addr));
}

// split v into fp16 hi + fp16 lo (residual)
__device__ __forceinline__ void split_h2(float x, float y, __half2& hi, __half2& lo) {
    hi = __floats2half2_rn(x, y);
    lo = __floats2half2_rn(x - __low2float(hi), y - __high2float(hi));
}

// ---------------------------------------------------------------------------
// Pre-pass: f32 -> f16 (RN). Each thread converts 8 values (16B store).
// ---------------------------------------------------------------------------
__global__ void to_half(const float* __restrict__ in, __half* __restrict__ out, int n8) {
    int i = blockIdx.x * 256 + threadIdx.x;
    if (i >= n8) return;
    float4 v0 = ((const float4*)in)[2 * i];
    float4 v1 = ((const float4*)in)[2 * i + 1];
    __half2 h[4];
    h[0] = __floats2half2_rn(v0.x, v0.y);
    h[1] = __floats2half2_rn(v0.z, v0.w);
    h[2] = __floats2half2_rn(v1.x, v1.y);
    h[3] = __floats2half2_rn(v1.z, v1.w);
    ((uint4*)out)[i] = *(uint4*)h;
}

// ---------------------------------------------------------------------------
// Kernel 1: qkv = xh @ wh^T + b  (fp16 mma m16n8k16, cp.async 3-stage)
// BM=256, BN=128, BK=32 halves. 512 threads = 16 warps as 4(m) x 4(n);
// warp tile 64x32. SMEM rows stride 80B -> conflict-free ldmatrix.
// ---------------------------------------------------------------------------
__global__ __launch_bounds__(512, 1)
void qkv_gemm_f16(const __half* __restrict__ xh,
                  const __half* __restrict__ wh,
                  const float* __restrict__ bias_vec) {
    extern __shared__ char smem[];   // STAGES * (A 20480 + B 10240)
    const uint32_t smem_base = (uint32_t)__cvta_generic_to_shared(smem);

    const int tid  = threadIdx.x;
    const int lane = tid & 31, warp = tid >> 5;
    const int wm = warp >> 2, wn = warp & 3;        // 4 x 4 warp grid
    const int bm = blockIdx.y * 256, bn = blockIdx.x * 128;

    // loader: A 1024 granules (2/thread), B 512 granules (1/thread), 16B each
    const __half* aptr[2];
    uint32_t aoff[2];
#pragma unroll
    for (int i = 0; i < 2; ++i) {
        const int id  = i * 512 + tid;              // 0..1023
        const int row = id >> 2, c = id & 3;
        aoff[i] = (uint32_t)(row * ROWB + c * 16);
        aptr[i] = xh + (size_t)(bm + row) * D_MODEL + c * 8;
    }
    const int brow = tid >> 2, bc = tid & 3;
    const uint32_t boff = (uint32_t)(brow * ROWB + bc * 16);
    const __half* bptr = wh + (size_t)(bn + brow) * D_MODEL + bc * 8;

    auto issue = [&](int kt, int s) {
        const uint32_t ab = smem_base + s * STAGEB;
        const uint32_t bb = ab + ATILEB;
#pragma unroll
        for (int i = 0; i < 2; ++i)
            asm volatile("cp.async.cg.shared.global [%0], [%1], 16;"
                         :: "r"(ab + aoff[i]), "l"(aptr[i] + kt * 32));
        asm volatile("cp.async.cg.shared.global [%0], [%1], 16;"
                     :: "r"(bb + boff), "l"(bptr + kt * 32));
        asm volatile("cp.async.commit_group;");
    };

    float acc[4][4][4];
#pragma unroll
    for (int m = 0; m < 4; ++m)
#pragma unroll
        for (int n = 0; n < 4; ++n)
#pragma unroll
            for (int q = 0; q < 4; ++q) acc[m][n][q] = 0.f;

    const int laneR8 = lane & 7;
    const int aRow   = laneR8 + ((lane >> 3) & 1) * 8;
    const int aChunk = lane >> 4;
    const int bRow   = laneR8;
    const int bChunk = (lane >> 3) & 1;

    issue(0, 0);
    issue(1, 1);

    for (int kt = 0; kt < NKT; ++kt) {
        if (kt == NKT - 1) asm volatile("cp.async.wait_group 0;");
        else               asm volatile("cp.async.wait_group 1;");
        __syncthreads();

        const int s = kt % STAGES;
        const uint32_t abase = smem_base + s * STAGEB;
        const uint32_t bbase = abase + ATILEB;

#pragma unroll
        for (int ks = 0; ks < 2; ++ks) {
            uint32_t af[4][4];
#pragma unroll
            for (int mf = 0; mf < 4; ++mf) {
                const int row = wm * 64 + mf * 16 + aRow;
                ldsm4(af[mf][0], af[mf][1], af[mf][2], af[mf][3],
                      abase + (uint32_t)(row * ROWB + (ks * 2 + aChunk) * 16));
            }
            uint32_t bf[4][2];
#pragma unroll
            for (int nf = 0; nf < 4; ++nf) {
                const int row = wn * 32 + nf * 8 + bRow;
                ldsm2(bf[nf][0], bf[nf][1],
                      bbase + (uint32_t)(row * ROWB + (ks * 2 + bChunk) * 16));
            }
#pragma unroll
            for (int mf = 0; mf < 4; ++mf)
#pragma unroll
                for (int nf = 0; nf < 4; ++nf)
                    mma_f16(acc[mf][nf], af[mf], bf[nf][0], bf[nf][1]);
        }

        if (kt + 2 < NKT) issue(kt + 2, (kt + 2) % STAGES);
    }

    // ---- epilogue: bias + q-scale + store (f32)
    const float scale = (blockIdx.x < 4) ? SCALE_Q : 1.0f;
    const int gq = lane >> 2, tq = lane & 3;
#pragma unroll
    for (int n = 0; n < 4; ++n) {
        const int col = bn + wn * 32 + n * 8 + tq * 2;
        const float bx = bias_vec[col];
        const float by = bias_vec[col + 1];
#pragma unroll
        for (int m = 0; m < 4; ++m) {
            const int row0 = bm + wm * 64 + m * 16 + gq;
            float* o0 = &g_qkv[(size_t)row0 * THREE_D + col];
            *(float2*)o0 = make_float2((acc[m][n][0] + bx) * scale,
                                       (acc[m][n][1] + by) * scale);
            float* o1 = o0 + (size_t)8 * THREE_D;
            *(float2*)o1 = make_float2((acc[m][n][2] + bx) * scale,
                                       (acc[m][n][3] + by) * scale);
        }
    }
}

// ---------------------------------------------------------------------------
// Kernel 2: per (window, head) attention via split-fp16 mma.
// 128 threads / 4 warps; warp w owns rows 16w..16w+15.
// Q/K/V/P pre-split into fp16 hi/lo in SMEM; mainloop = LDS.32 + HMMA only.
// Strides (halves): Q/K 40, Vt/P 72  -> all fragment loads conflict-free.
// ---------------------------------------------------------------------------
__device__ __forceinline__ int region_id(int g) {
    return g < 56 ? 0 : (g < 60 ? 1 : 2);
}

#define SQK 40
#define SVP 72

__global__ __launch_bounds__(128)
void win_attn_f16(const float* __restrict__ bias_table, float* __restrict__ out) {
    const int head = blockIdx.x;
    const int wdx  = blockIdx.y;
    const int n  = wdx >> 6;
    const int rr = wdx & 63;
    const int wh = rr >> 3;
    const int ww = rr & 7;

    __shared__ __half Qh[64 * SQK], Ql[64 * SQK];
    __shared__ __half Kh[64 * SQK], Kl[64 * SQK];
    __shared__ __half Vth[32 * SVP], Vtl[32 * SVP];   // transposed: [d][j]
    __shared__ __half Ph[64 * SVP], Pl[64 * SVP];
    __shared__ float bias_s[228];

    const int tid  = threadIdx.x;
    const int lane = tid & 31, warp = tid >> 5;
    const int ra  = lane >> 2;         // fragment row/col lane decomposition
    const int ca2 = (lane & 3) * 2;

    for (int i = tid; i < 225; i += 128)
        bias_s[i] = bias_table[i * N_HEAD + head];

    // ---- load Q, K (row-major, split) ----
#pragma unroll
    for (int pass = 0; pass < 4; ++pass) {
        const int idx = pass * 128 + tid;           // 0..511
        const int row = idx >> 3;
        const int c4  = (idx & 7) * 4;
        const int tok = ((n * 64 + wh * 8 + (row >> 3)) * 64 + ww * 8 + (row & 7));
        const float* base = g_qkv + (size_t)tok * THREE_D + head * HEAD_DIM + c4;
        float4 qv = *(const float4*)(base);
        float4 kv = *(const float4*)(base + 512);
        __half2 h01, l01, h23, l23;
        split_h2(qv.x, qv.y, h01, l01);
        split_h2(qv.z, qv.w, h23, l23);
        *(__half2*)&Qh[row * SQK + c4]     = h01;
        *(__half2*)&Qh[row * SQK + c4 + 2] = h23;
        *(__half2*)&Ql[row * SQK + c4]     = l01;
        *(__half2*)&Ql[row * SQK + c4 + 2] = l23;
        split_h2(kv.x, kv.y, h01, l01);
        split_h2(kv.z, kv.w, h23, l23);
        *(__half2*)&Kh[row * SQK + c4]     = h01;
        *(__half2*)&Kh[row * SQK + c4 + 2] = h23;
        *(__half2*)&Kl[row * SQK + c4]     = l01;
        *(__half2*)&Kl[row * SQK + c4 + 2] = l23;
    }

    // ---- load V transposed (split): thread handles j-pair x 4 d ----
#pragma unroll
    for (int pass = 0; pass < 2; ++pass) {
        const int idx = pass * 128 + tid;           // 0..255
        const int jp  = idx & 31;                   // j pair index
        const int d4  = (idx >> 5) * 4;
        const int j0  = 2 * jp, j1 = 2 * jp + 1;
        const int t0 = ((n * 64 + wh * 8 + (j0 >> 3)) * 64 + ww * 8 + (j0 & 7));
        const int t1 = ((n * 64 + wh * 8 + (j1 >> 3)) * 64 + ww * 8 + (j1 & 7));
        float4 v0 = *(const float4*)(g_qkv + (size_t)t0 * THREE_D + head * HEAD_DIM + 1024 + d4);
        float4 v1 = *(const float4*)(g_qkv + (size_t)t1 * THREE_D + head * HEAD_DIM + 1024 + d4);
        const float a0[4] = {v0.x, v0.y, v0.z, v0.w};
        const float a1[4] = {v1.x, v1.y, v1.z, v1.w};
#pragma unroll
        for (int u = 0; u < 4; ++u) {
            __half2 h, l;
            split_h2(a0[u], a1[u], h, l);
            *(__half2*)&Vth[(d4 + u) * SVP + j0] = h;
            *(__half2*)&Vtl[(d4 + u) * SVP + j0] = l;
        }
    }
    __syncthreads();

    const int m0 = warp * 16;

    // ---- phase 1: S = Q K^T  (per warp 16x64, k=32; split-fp16, 3 mma/term)
    float acc[8][4];
#pragma unroll
    for (int nf = 0; nf < 8; ++nf)
#pragma unroll
        for (int q = 0; q < 4; ++q) acc[nf][q] = 0.f;

#pragma unroll
    for (int ks = 0; ks < 2; ++ks) {
        const int k0 = ks * 16;
        const int ro = (m0 + ra) * SQK + k0 + ca2;
        uint32_t ah[4], al[4];
        ah[0] = *(const uint32_t*)&Qh[ro];
        ah[1] = *(const uint32_t*)&Qh[ro + 8 * SQK];
        ah[2] = *(const uint32_t*)&Qh[ro + 8];
        ah[3] = *(const uint32_t*)&Qh[ro + 8 * SQK + 8];
        al[0] = *(const uint32_t*)&Ql[ro];
        al[1] = *(const uint32_t*)&Ql[ro + 8 * SQK];
        al[2] = *(const uint32_t*)&Ql[ro + 8];
        al[3] = *(const uint32_t*)&Ql[ro + 8 * SQK + 8];
#pragma unroll
        for (int nf = 0; nf < 8; ++nf) {
            const int ko = (nf * 8 + ra) * SQK + k0 + ca2;
            const uint32_t bh0 = *(const uint32_t*)&Kh[ko];
            const uint32_t bh1 = *(const uint32_t*)&Kh[ko + 8];
            const uint32_t bl0 = *(const uint32_t*)&Kl[ko];
            const uint32_t bl1 = *(const uint32_t*)&Kl[ko + 8];
            mma_f16(acc[nf], ah, bh0, bh1);
            mma_f16(acc[nf], ah, bl0, bl1);
            mma_f16(acc[nf], al, bh0, bh1);
        }
    }

    // ---- phase 2: bias + mask + row softmax in C regs; store split P
#pragma unroll
    for (int h = 0; h < 2; ++h) {
        const int i  = m0 + ra + 8 * h;
        const int ih = i >> 3, iw = i & 7;
        const int mi = region_id(wh * 8 + ih) * 3 + region_id(ww * 8 + iw);

        float vals[16];
#pragma unroll
        for (int nf = 0; nf < 8; ++nf) {
            const int d0row = (ih - nf + 7) * 15;
            const int regh3 = region_id(wh * 8 + nf) * 3;
#pragma unroll
            for (int e = 0; e < 2; ++e) {
                const int j = ca2 + e;
                float v = acc[nf][2 * h + e] + bias_s[d0row + (iw - j + 7)];
                if (mi != regh3 + region_id(ww * 8 + j)) v -= 100.f;
                vals[nf * 2 + e] = v;
            }
        }
        float mx = vals[0];
#pragma unroll
        for (int q = 1; q < 16; ++q) mx = fmaxf(mx, vals[q]);
        mx = fmaxf(mx, __shfl_xor_sync(0xffffffffu, mx, 1));
        mx = fmaxf(mx, __shfl_xor_sync(0xffffffffu, mx, 2));
        float sum = 0.f;
#pragma unroll
        for (int q = 0; q < 16; ++q) { vals[q] = __expf(vals[q] - mx); sum += vals[q]; }
        sum += __shfl_xor_sync(0xffffffffu, sum, 1);
        sum += __shfl_xor_sync(0xffffffffu, sum, 2);
        const float inv = 1.0f / sum;
#pragma unroll
        for (int nf = 0; nf < 8; ++nf) {
            __half2 hp, lp;
            split_h2(vals[nf * 2] * inv, vals[nf * 2 + 1] * inv, hp, lp);
            *(__half2*)&Ph[i * SVP + nf * 8 + ca2] = hp;
            *(__half2*)&Pl[i * SVP + nf * 8 + ca2] = lp;
        }
    }
    __syncwarp();   // P rows are warp-private: warp-level visibility suffices

    // ---- phase 3: O = P V  (per warp 16x32, k=64; split-fp16)
    float oacc[4][4];
#pragma unroll
    for (int nf = 0; nf < 4; ++nf)
#pragma unroll
        for (int q = 0; q < 4; ++q) oacc[nf][q] = 0.f;

#pragma unroll
    for (int ks = 0; ks < 4; ++ks) {
        const int k0 = ks * 16;
        const int po = (m0 + ra) * SVP + k0 + ca2;
        uint32_t ah[4], al[4];
        ah[0] = *(const uint32_t*)&Ph[po];
        ah[1] = *(const uint32_t*)&Ph[po + 8 * SVP];
        ah[2] = *(const uint32_t*)&Ph[po + 8];
        ah[3] = *(const uint32_t*)&Ph[po + 8 * SVP + 8];
        al[0] = *(const uint32_t*)&Pl[po];
        al[1] = *(const uint32_t*)&Pl[po + 8 * SVP];
        al[2] = *(const uint32_t*)&Pl[po + 8];
        al[3] = *(const uint32_t*)&Pl[po + 8 * SVP + 8];
#pragma unroll
        for (int nf = 0; nf < 4; ++nf) {
            const int vo = (nf * 8 + ra) * SVP + k0 + ca2;
            const uint32_t bh0 = *(const uint32_t*)&Vth[vo];
            const uint32_t bh1 = *(const uint32_t*)&Vth[vo + 8];
            const uint32_t bl0 = *(const uint32_t*)&Vtl[vo];
            const uint32_t bl1 = *(const uint32_t*)&Vtl[vo + 8];
            mma_f16(oacc[nf], ah, bh0, bh1);
            mma_f16(oacc[nf], ah, bl0, bl1);
            mma_f16(oacc[nf], al, bh0, bh1);
        }
    }

    // ---- write output in (n,H,W,c) layout
#pragma unroll
    for (int nf = 0; nf < 4; ++nf)
#pragma unroll
        for (int h = 0; h < 2; ++h) {
            const int i   = m0 + ra + 8 * h;
            const int tok = ((n * 64 + wh * 8 + (i >> 3)) * 64 + ww * 8 + (i & 7));
            float2* dst = (float2*)(out + (size_t)tok * D_MODEL + head * HEAD_DIM
                                    + nf * 8 + ca2);
            *dst = make_float2(oacc[nf][2 * h], oacc[nf][2 * h + 1]);
        }
}

// ---------------------------------------------------------------------------
extern "C" void kernel_launch(void* const* d_in, const int* in_sizes, int n_in,
                              void* d_out, int out_size) {
    const float* x  = (const float*)d_in[0];   // (8,64,64,512) f32
    const float* w  = (const float*)d_in[1];   // (1536,512)   f32
    const float* b  = (const float*)d_in[2];   // (1536,)      f32
    const float* bt = (const float*)d_in[3];   // (225,16)     f32
    float* out = (float*)d_out;                // (8,64,64,512) f32

    __half* xh; cudaGetSymbolAddress((void**)&xh, g_xh);
    __half* wh; cudaGetSymbolAddress((void**)&wh, g_wh);

    const int n8x = M_TOK * D_MODEL / 8;       // 2097152
    const int n8w = THREE_D * D_MODEL / 8;     // 98304
    to_half<<<(n8x + 255) / 256, 256>>>(x, xh, n8x);
    to_half<<<(n8w + 255) / 256, 256>>>(w, wh, n8w);

    cudaFuncSetAttribute(qkv_gemm_f16, cudaFuncAttributeMaxDynamicSharedMemorySize,
                         STAGES * STAGEB);
    dim3 g1(THREE_D / 128, M_TOK / 256);       // (12, 128)
    qkv_gemm_f16<<<g1, 512, STAGES * STAGEB>>>(xh, wh, b);

    dim3 g2(N_HEAD, 512);                      // head, window
    win_attn_f16<<<g2, 128>>>(bt, out);
}

// round 9
// speedup vs baseline: 5.1211x; 1.0704x over previous
#include <cuda_runtime.h>
#include <cuda_fp16.h>
#include <cstdint>

#define D_MODEL   512
#define THREE_D   1536
#define M_TOK     32768      // 8 * 64 * 64 tokens
#define N_HEAD    16
#define HEAD_DIM  32
#define SCALE_Q   0.17677669529663689f   // 1/sqrt(32)
#define STAGES    3
#define NKT       16         // 512 / 32 halves per k-tile
#define ROWB      80         // smem row stride bytes (32 halves + 16B pad)
#define TILEB     (128 * ROWB)          // 10240 per operand tile
#define STAGEB    (2 * TILEB)           // 20480 per stage

// Device-global scratch (allocation-guard-safe)
__device__ float  g_qkv[(size_t)M_TOK * THREE_D];        // 201 MB
__device__ __half g_xh[(size_t)M_TOK * D_MODEL];         // 32 MB  fp16 x
__device__ __half g_wh[(size_t)THREE_D * D_MODEL];       // 1.5 MB fp16 w

__device__ __forceinline__ void mma_f16(float* c, const uint32_t* a,
                                        uint32_t b0, uint32_t b1) {
    asm volatile(
        "mma.sync.aligned.m16n8k16.row.col.f32.f16.f16.f32 "
        "{%0,%1,%2,%3}, {%4,%5,%6,%7}, {%8,%9}, {%0,%1,%2,%3};\n"
        : "+f"(c[0]), "+f"(c[1]), "+f"(c[2]), "+f"(c[3])
        : "r"(a[0]), "r"(a[1]), "r"(a[2]), "r"(a[3]), "r"(b0), "r"(b1));
}

__device__ __forceinline__ void ldsm4(uint32_t& r0, uint32_t& r1, uint32_t& r2,
                                      uint32_t& r3, uint32_t addr) {
    asm volatile("ldmatrix.sync.aligned.m8n8.x4.shared.b16 {%0,%1,%2,%3}, [%4];"
                 : "=r"(r0), "=r"(r1), "=r"(r2), "=r"(r3) : "r"(addr));
}

__device__ __forceinline__ void ldsm2(uint32_t& r0, uint32_t& r1, uint32_t addr) {
    asm volatile("ldmatrix.sync.aligned.m8n8.x2.shared.b16 {%0,%1}, [%2];"
                 : "=r"(r0), "=r"(r1) : "r"(addr));
}

// split (x,y) into fp16 hi + fp16 lo (residual), both as packed half2
__device__ __forceinline__ void split_h2(float x, float y, __half2& hi, __half2& lo) {
    hi = __floats2half2_rn(x, y);
    lo = __floats2half2_rn(x - __low2float(hi), y - __high2float(hi));
}

__device__ __forceinline__ uint32_t h2u(__half2 h) {
    return *reinterpret_cast<uint32_t*>(&h);
}

// ---------------------------------------------------------------------------
// Pre-pass: f32 -> f16 (RN). Each thread converts 8 values (16B store).
// ---------------------------------------------------------------------------
__global__ void to_half(const float* __restrict__ in, __half* __restrict__ out, int n8) {
    int i = blockIdx.x * 256 + threadIdx.x;
    if (i >= n8) return;
    float4 v0 = ((const float4*)in)[2 * i];
    float4 v1 = ((const float4*)in)[2 * i + 1];
    __half2 h[4];
    h[0] = __floats2half2_rn(v0.x, v0.y);
    h[1] = __floats2half2_rn(v0.z, v0.w);
    h[2] = __floats2half2_rn(v1.x, v1.y);
    h[3] = __floats2half2_rn(v1.z, v1.w);
    ((uint4*)out)[i] = *(uint4*)h;
}

// ---------------------------------------------------------------------------
// Kernel 1: qkv = xh @ wh^T + b  (fp16 mma m16n8k16, cp.async 3-stage)
// BM=BN=128, BK=32 halves. 256 threads = 8 warps as 2(m) x 4(n);
// warp tile 64x32. (R7 config — 2 CTAs/SM.)
// ---------------------------------------------------------------------------
__global__ __launch_bounds__(256, 2)
void qkv_gemm_f16(const __half* __restrict__ xh,
                  const __half* __restrict__ wh,
                  const float* __restrict__ bias_vec) {
    extern __shared__ char smem[];   // STAGES * (A 10240 + B 10240)
    const uint32_t smem_base = (uint32_t)__cvta_generic_to_shared(smem);

    const int tid  = threadIdx.x;
    const int lane = tid & 31, warp = tid >> 5;
    const int wm = warp >> 2, wn = warp & 3;        // 2 x 4 warp grid
    const int bm = blockIdx.y * 128, bn = blockIdx.x * 128;

    const __half* aptr[2];
    const __half* bptr[2];
    uint32_t soff[2];
#pragma unroll
    for (int i = 0; i < 2; ++i) {
        const int id  = i * 256 + tid;              // 0..511
        const int row = id >> 2, c = id & 3;
        soff[i] = (uint32_t)(row * ROWB + c * 16);
        aptr[i] = xh + (size_t)(bm + row) * D_MODEL + c * 8;
        bptr[i] = wh + (size_t)(bn + row) * D_MODEL + c * 8;
    }

    auto issue = [&](int kt, int s) {
        const uint32_t ab = smem_base + s * STAGEB;
        const uint32_t bb = ab + TILEB;
#pragma unroll
        for (int i = 0; i < 2; ++i) {
            asm volatile("cp.async.cg.shared.global [%0], [%1], 16;"
                         :: "r"(ab + soff[i]), "l"(aptr[i] + kt * 32));
            asm volatile("cp.async.cg.shared.global [%0], [%1], 16;"
                         :: "r"(bb + soff[i]), "l"(bptr[i] + kt * 32));
        }
        asm volatile("cp.async.commit_group;");
    };

    float acc[4][4][4];
#pragma unroll
    for (int m = 0; m < 4; ++m)
#pragma unroll
        for (int n = 0; n < 4; ++n)
#pragma unroll
            for (int q = 0; q < 4; ++q) acc[m][n][q] = 0.f;

    const int laneR8 = lane & 7;
    const int aRow   = laneR8 + ((lane >> 3) & 1) * 8;
    const int aChunk = lane >> 4;
    const int bRow   = laneR8;
    const int bChunk = (lane >> 3) & 1;

    issue(0, 0);
    issue(1, 1);

    for (int kt = 0; kt < NKT; ++kt) {
        if (kt == NKT - 1) asm volatile("cp.async.wait_group 0;");
        else               asm volatile("cp.async.wait_group 1;");
        __syncthreads();

        const int s = kt % STAGES;
        const uint32_t abase = smem_base + s * STAGEB;
        const uint32_t bbase = abase + TILEB;

#pragma unroll
        for (int ks = 0; ks < 2; ++ks) {
            uint32_t af[4][4];
#pragma unroll
            for (int mf = 0; mf < 4; ++mf) {
                const int row = wm * 64 + mf * 16 + aRow;
                ldsm4(af[mf][0], af[mf][1], af[mf][2], af[mf][3],
                      abase + (uint32_t)(row * ROWB + (ks * 2 + aChunk) * 16));
            }
            uint32_t bf[4][2];
#pragma unroll
            for (int nf = 0; nf < 4; ++nf) {
                const int row = wn * 32 + nf * 8 + bRow;
                ldsm2(bf[nf][0], bf[nf][1],
                      bbase + (uint32_t)(row * ROWB + (ks * 2 + bChunk) * 16));
            }
#pragma unroll
            for (int mf = 0; mf < 4; ++mf)
#pragma unroll
                for (int nf = 0; nf < 4; ++nf)
                    mma_f16(acc[mf][nf], af[mf], bf[nf][0], bf[nf][1]);
        }

        if (kt + 2 < NKT) issue(kt + 2, (kt + 2) % STAGES);
    }

    // ---- epilogue: bias + q-scale + store (f32)
    const float scale = (blockIdx.x < 4) ? SCALE_Q : 1.0f;
    const int gq = lane >> 2, tq = lane & 3;
#pragma unroll
    for (int n = 0; n < 4; ++n) {
        const int col = bn + wn * 32 + n * 8 + tq * 2;
        const float bx = bias_vec[col];
        const float by = bias_vec[col + 1];
#pragma unroll
        for (int m = 0; m < 4; ++m) {
            const int row0 = bm + wm * 64 + m * 16 + gq;
            float* o0 = &g_qkv[(size_t)row0 * THREE_D + col];
            *(float2*)o0 = make_float2((acc[m][n][0] + bx) * scale,
                                       (acc[m][n][1] + by) * scale);
            float* o1 = o0 + (size_t)8 * THREE_D;
            *(float2*)o1 = make_float2((acc[m][n][2] + bx) * scale,
                                       (acc[m][n][3] + by) * scale);
        }
    }
}

// ---------------------------------------------------------------------------
// Kernel 2: per (window, head) attention via split-fp16 mma.
// P stays in registers (C-frag of S == A-frag halves for PV) -> no P smem,
// no sync between softmax and PV. SMEM ~31KB -> higher occupancy.
// ---------------------------------------------------------------------------
__device__ __forceinline__ int region_id(int g) {
    return g < 56 ? 0 : (g < 60 ? 1 : 2);
}

#define SQK 40
#define SVP 72

__global__ __launch_bounds__(128, 5)
void win_attn_f16(const float* __restrict__ bias_table, float* __restrict__ out) {
    const int head = blockIdx.x;
    const int wdx  = blockIdx.y;
    const int n  = wdx >> 6;
    const int rr = wdx & 63;
    const int wh = rr >> 3;
    const int ww = rr & 7;

    __shared__ __half Qh[64 * SQK], Ql[64 * SQK];
    __shared__ __half Kh[64 * SQK], Kl[64 * SQK];
    __shared__ __half Vth[32 * SVP], Vtl[32 * SVP];   // transposed: [d][j]
    __shared__ float bias_s[228];

    const int tid  = threadIdx.x;
    const int lane = tid & 31, warp = tid >> 5;
    const int ra  = lane >> 2;
    const int ca2 = (lane & 3) * 2;

    for (int i = tid; i < 225; i += 128)
        bias_s[i] = bias_table[i * N_HEAD + head];

    // ---- load Q, K (row-major, split) ----
#pragma unroll
    for (int pass = 0; pass < 4; ++pass) {
        const int idx = pass * 128 + tid;           // 0..511
        const int row = idx >> 3;
        const int c4  = (idx & 7) * 4;
        const int tok = ((n * 64 + wh * 8 + (row >> 3)) * 64 + ww * 8 + (row & 7));
        const float* base = g_qkv + (size_t)tok * THREE_D + head * HEAD_DIM + c4;
        float4 qv = *(const float4*)(base);
        float4 kv = *(const float4*)(base + 512);
        __half2 h01, l01, h23, l23;
        split_h2(qv.x, qv.y, h01, l01);
        split_h2(qv.z, qv.w, h23, l23);
        *(__half2*)&Qh[row * SQK + c4]     = h01;
        *(__half2*)&Qh[row * SQK + c4 + 2] = h23;
        *(__half2*)&Ql[row * SQK + c4]     = l01;
        *(__half2*)&Ql[row * SQK + c4 + 2] = l23;
        split_h2(kv.x, kv.y, h01, l01);
        split_h2(kv.z, kv.w, h23, l23);
        *(__half2*)&Kh[row * SQK + c4]     = h01;
        *(__half2*)&Kh[row * SQK + c4 + 2] = h23;
        *(__half2*)&Kl[row * SQK + c4]     = l01;
        *(__half2*)&Kl[row * SQK + c4 + 2] = l23;
    }

    // ---- load V transposed (split) ----
#pragma unroll
    for (int pass = 0; pass < 2; ++pass) {
        const int idx = pass * 128 + tid;           // 0..255
        const int jp  = idx & 31;
        const int d4  = (idx >> 5) * 4;
        const int j0  = 2 * jp, j1 = 2 * jp + 1;
        const int t0 = ((n * 64 + wh * 8 + (j0 >> 3)) * 64 + ww * 8 + (j0 & 7));
        const int t1 = ((n * 64 + wh * 8 + (j1 >> 3)) * 64 + ww * 8 + (j1 & 7));
        float4 v0 = *(const float4*)(g_qkv + (size_t)t0 * THREE_D + head * HEAD_DIM + 1024 + d4);
        float4 v1 = *(const float4*)(g_qkv + (size_t)t1 * THREE_D + head * HEAD_DIM + 1024 + d4);
        const float a0[4] = {v0.x, v0.y, v0.z, v0.w};
        const float a1[4] = {v1.x, v1.y, v1.z, v1.w};
#pragma unroll
        for (int u = 0; u < 4; ++u) {
            __half2 h, l;
            split_h2(a0[u], a1[u], h, l);
            *(__half2*)&Vth[(d4 + u) * SVP + j0] = h;
            *(__half2*)&Vtl[(d4 + u) * SVP + j0] = l;
        }
    }
    __syncthreads();

    const int m0 = warp * 16;

    // ---- phase 1: S = Q K^T ----
    float acc[8][4];
#pragma unroll
    for (int nf = 0; nf < 8; ++nf)
#pragma unroll
        for (int q = 0; q < 4; ++q) acc[nf][q] = 0.f;

#pragma unroll
    for (int ks = 0; ks < 2; ++ks) {
        const int k0 = ks * 16;
        const int ro = (m0 + ra) * SQK + k0 + ca2;
        uint32_t ah[4], al[4];
        ah[0] = *(const uint32_t*)&Qh[ro];
        ah[1] = *(const uint32_t*)&Qh[ro + 8 * SQK];
        ah[2] = *(const uint32_t*)&Qh[ro + 8];
        ah[3] = *(const uint32_t*)&Qh[ro + 8 * SQK + 8];
        al[0] = *(const uint32_t*)&Ql[ro];
        al[1] = *(const uint32_t*)&Ql[ro + 8 * SQK];
        al[2] = *(const uint32_t*)&Ql[ro + 8];
        al[3] = *(const uint32_t*)&Ql[ro + 8 * SQK + 8];
#pragma unroll
        for (int nf = 0; nf < 8; ++nf) {
            const int ko = (nf * 8 + ra) * SQK + k0 + ca2;
            const uint32_t bh0 = *(const uint32_t*)&Kh[ko];
            const uint32_t bh1 = *(const uint32_t*)&Kh[ko + 8];
            const uint32_t bl0 = *(const uint32_t*)&Kl[ko];
            const uint32_t bl1 = *(const uint32_t*)&Kl[ko + 8];
            mma_f16(acc[nf], ah, bh0, bh1);
            mma_f16(acc[nf], ah, bl0, bl1);
            mma_f16(acc[nf], al, bh0, bh1);
        }
    }

    // ---- phase 2: bias + mask + softmax; keep P in registers ----
    float pv[2][16];   // pv[h][nf*2+e] = P[ra+8h][nf*8+ca2+e]
#pragma unroll
    for (int h = 0; h < 2; ++h) {
        const int i  = m0 + ra + 8 * h;
        const int ih = i >> 3, iw = i & 7;
        const int mi = region_id(wh * 8 + ih) * 3 + region_id(ww * 8 + iw);

#pragma unroll
        for (int nf = 0; nf < 8; ++nf) {
            const int d0row = (ih - nf + 7) * 15;
            const int regh3 = region_id(wh * 8 + nf) * 3;
#pragma unroll
            for (int e = 0; e < 2; ++e) {
                const int j = ca2 + e;
                float v = acc[nf][2 * h + e] + bias_s[d0row + (iw - j + 7)];
                if (mi != regh3 + region_id(ww * 8 + j)) v -= 100.f;
                pv[h][nf * 2 + e] = v;
            }
        }
        float mx = pv[h][0];
#pragma unroll
        for (int q = 1; q < 16; ++q) mx = fmaxf(mx, pv[h][q]);
        mx = fmaxf(mx, __shfl_xor_sync(0xffffffffu, mx, 1));
        mx = fmaxf(mx, __shfl_xor_sync(0xffffffffu, mx, 2));
        float sum = 0.f;
#pragma unroll
        for (int q = 0; q < 16; ++q) { pv[h][q] = __expf(pv[h][q] - mx); sum += pv[h][q]; }
        sum += __shfl_xor_sync(0xffffffffu, sum, 1);
        sum += __shfl_xor_sync(0xffffffffu, sum, 2);
        const float inv = 1.0f / sum;
#pragma unroll
        for (int q = 0; q < 16; ++q) pv[h][q] *= inv;
    }

    // ---- phase 3: O = P V, P A-frags built in registers ----
    float oacc[4][4];
#pragma unroll
    for (int nf = 0; nf < 4; ++nf)
#pragma unroll
        for (int q = 0; q < 4; ++q) oacc[nf][q] = 0.f;

#pragma unroll
    for (int ks = 0; ks < 4; ++ks) {
        const int k0 = ks * 16;
        uint32_t ah[4], al[4];
        {
            __half2 h, l;
            split_h2(pv[0][4 * ks + 0], pv[0][4 * ks + 1], h, l);  // row ra,  k ca2
            ah[0] = h2u(h); al[0] = h2u(l);
            split_h2(pv[1][4 * ks + 0], pv[1][4 * ks + 1], h, l);  // row ra+8
            ah[1] = h2u(h); al[1] = h2u(l);
            split_h2(pv[0][4 * ks + 2], pv[0][4 * ks + 3], h, l);  // row ra,  k ca2+8
            ah[2] = h2u(h); al[2] = h2u(l);
            split_h2(pv[1][4 * ks + 2], pv[1][4 * ks + 3], h, l);  // row ra+8
            ah[3] = h2u(h); al[3] = h2u(l);
        }
#pragma unroll
        for (int nf = 0; nf < 4; ++nf) {
            const int vo = (nf * 8 + ra) * SVP + k0 + ca2;
            const uint32_t bh0 = *(const uint32_t*)&Vth[vo];
            const uint32_t bh1 = *(const uint32_t*)&Vth[vo + 8];
            const uint32_t bl0 = *(const uint32_t*)&Vtl[vo];
            const uint32_t bl1 = *(const uint32_t*)&Vtl[vo + 8];
            mma_f16(oacc[nf], ah, bh0, bh1);
            mma_f16(oacc[nf], ah, bl0, bl1);
            mma_f16(oacc[nf], al, bh0, bh1);
        }
    }

    // ---- write output in (n,H,W,c) layout
#pragma unroll
    for (int nf = 0; nf < 4; ++nf)
#pragma unroll
        for (int h = 0; h < 2; ++h) {
            const int i   = m0 + ra + 8 * h;
            const int tok = ((n * 64 + wh * 8 + (i >> 3)) * 64 + ww * 8 + (i & 7));
            float2* dst = (float2*)(out + (size_t)tok * D_MODEL + head * HEAD_DIM
                                    + nf * 8 + ca2);
            *dst = make_float2(oacc[nf][2 * h], oacc[nf][2 * h + 1]);
        }
}

// ---------------------------------------------------------------------------
extern "C" void kernel_launch(void* const* d_in, const int* in_sizes, int n_in,
                              void* d_out, int out_size) {
    const float* x  = (const float*)d_in[0];   // (8,64,64,512) f32
    const float* w  = (const float*)d_in[1];   // (1536,512)   f32
    const float* b  = (const float*)d_in[2];   // (1536,)      f32
    const float* bt = (const float*)d_in[3];   // (225,16)     f32
    float* out = (float*)d_out;                // (8,64,64,512) f32

    __half* xh; cudaGetSymbolAddress((void**)&xh, g_xh);
    __half* wh; cudaGetSymbolAddress((void**)&wh, g_wh);

    const int n8x = M_TOK * D_MODEL / 8;       // 2097152
    const int n8w = THREE_D * D_MODEL / 8;     // 98304
    to_half<<<(n8x + 255) / 256, 256>>>(x, xh, n8x);
    to_half<<<(n8w + 255) / 256, 256>>>(w, wh, n8w);

    cudaFuncSetAttribute(qkv_gemm_f16, cudaFuncAttributeMaxDynamicSharedMemorySize,
                         STAGES * STAGEB);
    dim3 g1(THREE_D / 128, M_TOK / 128);       // (12, 256)
    qkv_gemm_f16<<<g1, 256, STAGES * STAGEB>>>(xh, wh, b);

    dim3 g2(N_HEAD, 512);                      // head, window
    win_attn_f16<<<g2, 128>>>(bt, out);
}